// round 15
// baseline (speedup 1.0000x reference)
#include <cuda_runtime.h>
#include <cuda_bf16.h>
#include <mma.h>
#include <math.h>
#include <stdint.h>

using namespace nvcuda;

#define TT 128
#define LL 4
#define BB 64
#define HH 512
#define GG 16
#define FF 64
#define NREC 128
#define FIVEH (5*HH)
#define MTOT (BB*TT)   // 8192

// ---------------- scratch (device globals; no allocations) -------------------
__device__ __align__(128) float g_hh[(size_t)(TT+1)*LL*BB*HH];
__device__ __align__(128) float g_c[LL*BB*HH];
__device__ __align__(128) float g_xg[TT*LL*BB*GG];
__device__ unsigned char g_z[TT*LL*BB];
__device__ unsigned char g_allz[TT*LL];
__device__ float g_bt[LL*TT];
__device__ __align__(128) float g_part[TT*LL*NREC];
__device__ __align__(128) float g_pp[4*BB*4*HH];
__device__ unsigned int g_bar, g_bar2;
__device__ unsigned int g_flag1, g_flag2, g_flag3;
__device__ __align__(128) float g_excited[(size_t)MTOT*HH];

// bf16 split h-history + weights for the recurrence tensor path
__device__ __align__(128) __nv_bfloat16 g_hhbh[(size_t)(TT+1)*LL*BB*HH];
__device__ __align__(128) __nv_bfloat16 g_hhbl[(size_t)(TT+1)*LL*BB*HH];
__device__ __align__(128) __nv_bfloat16 g_Wbh[(size_t)LL*FIVEH*HH],      g_Wbl[(size_t)LL*FIVEH*HH];
__device__ __align__(128) __nv_bfloat16 g_Zbh[(size_t)LL*FIVEH*HH],      g_Zbl[(size_t)LL*FIVEH*HH];
__device__ __align__(128) __nv_bfloat16 g_Vbh[(size_t)LL*FIVEH*HH],      g_Vbl[(size_t)LL*FIVEH*HH];
__device__ __align__(128) __nv_bfloat16 g_Ubh[(size_t)LL*FIVEH*(HH+GG)], g_Ubl[(size_t)LL*FIVEH*(HH+GG)];
__device__ __align__(128) __nv_bfloat16 g_xgph[(size_t)TT*LL*BB*32], g_xgpl[(size_t)TT*LL*BB*32];
__device__ __align__(128) __nv_bfloat16 g_xUh[(size_t)LL*FIVEH*32],  g_xUl[(size_t)LL*FIVEH*32];
__device__ __align__(128) __nv_bfloat16 g_xJh[(size_t)LL*FIVEH*32],  g_xJl[(size_t)LL*FIVEH*32];

// bf16 split buffers for the excitation GEMMs (proven R10)
__device__ __align__(128) __nv_bfloat16 g_Ahi[(size_t)MTOT*2048];
__device__ __align__(128) __nv_bfloat16 g_Alo[(size_t)MTOT*2048];
__device__ __align__(128) __nv_bfloat16 g_QThi[(size_t)LL*HH*2048];
__device__ __align__(128) __nv_bfloat16 g_QTlo[(size_t)LL*HH*2048];
__device__ __align__(128) __nv_bfloat16 g_R1hi[(size_t)LL*MTOT*HH];
__device__ __align__(128) __nv_bfloat16 g_R1lo[(size_t)LL*MTOT*HH];
__device__ __align__(128) __nv_bfloat16 g_RmThi[(size_t)LL*HH*HH];
__device__ __align__(128) __nv_bfloat16 g_RmTlo[(size_t)LL*HH*HH];
__device__ __align__(128) float g_mul1[(size_t)LL*MTOT*HH];

__device__ __forceinline__ float sigf(float x){ return 1.f/(1.f+expf(-x)); }
__device__ __forceinline__ float clip01(float x){ return fminf(fmaxf(x,0.f),1.f); }
__device__ __forceinline__ void bsplit(float x, __nv_bfloat16& hi, __nv_bfloat16& lo){
  hi = __float2bfloat16(x);
  lo = __float2bfloat16(x - __bfloat162float(hi));
}

// ---------------- WMMA common ------------------------------------------------
#define SPAD 40

using FragA = wmma::fragment<wmma::matrix_a,16,16,16,__nv_bfloat16,wmma::row_major>;
using FragB = wmma::fragment<wmma::matrix_b,16,16,16,__nv_bfloat16,wmma::col_major>;
using FragC = wmma::fragment<wmma::accumulator,16,16,16,float>;

// 128x128 split-bf16 core for the excitation (proven in R10)
__device__ __forceinline__ void wmma_core(
    __nv_bfloat16* sm,
    const __nv_bfloat16* __restrict__ Ah, const __nv_bfloat16* __restrict__ Al, int lda,
    const __nv_bfloat16* __restrict__ Bh, const __nv_bfloat16* __restrict__ Bl, int ldb,
    int ktot, FragC (&acc)[2][4])
{
  __nv_bfloat16* sAh = sm;
  __nv_bfloat16* sAl = sm +   128*SPAD;
  __nv_bfloat16* sBh = sm + 2*128*SPAD;
  __nv_bfloat16* sBl = sm + 3*128*SPAD;
  const int tid = threadIdx.x, wid = tid >> 5;
  const int wm = wid & 3, wn = wid >> 2;

  for (int kc = 0; kc < ktot; kc += 32){
    #pragma unroll
    for (int id = tid; id < 512; id += 256){
      int row = id >> 2, q = id & 3;
      *(uint4*)&sAh[row*SPAD + q*8] = *(const uint4*)&Ah[(size_t)row*lda + kc + q*8];
      *(uint4*)&sAl[row*SPAD + q*8] = *(const uint4*)&Al[(size_t)row*lda + kc + q*8];
      *(uint4*)&sBh[row*SPAD + q*8] = *(const uint4*)&Bh[(size_t)row*ldb + kc + q*8];
      *(uint4*)&sBl[row*SPAD + q*8] = *(const uint4*)&Bl[(size_t)row*ldb + kc + q*8];
    }
    __syncthreads();
    #pragma unroll
    for (int ks = 0; ks < 32; ks += 16){
      FragA fah[2], fal[2];
      #pragma unroll
      for (int mi = 0; mi < 2; mi++){
        wmma::load_matrix_sync(fah[mi], &sAh[(wm*32 + mi*16)*SPAD + ks], SPAD);
        wmma::load_matrix_sync(fal[mi], &sAl[(wm*32 + mi*16)*SPAD + ks], SPAD);
      }
      #pragma unroll
      for (int ni = 0; ni < 4; ni++){
        FragB fbh, fbl;
        wmma::load_matrix_sync(fbh, &sBh[(wn*64 + ni*16)*SPAD + ks], SPAD);
        wmma::load_matrix_sync(fbl, &sBl[(wn*64 + ni*16)*SPAD + ks], SPAD);
        #pragma unroll
        for (int mi = 0; mi < 2; mi++){
          wmma::mma_sync(acc[mi][ni], fah[mi], fbh, acc[mi][ni]);
          wmma::mma_sync(acc[mi][ni], fal[mi], fbh, acc[mi][ni]);
          wmma::mma_sync(acc[mi][ni], fah[mi], fbl, acc[mi][ni]);
        }
      }
    }
    __syncthreads();
  }
}

// ---------------- fp32 SIMT GEMM helpers -------------------------------------
__device__ __forceinline__ void mm_inner(const float (*Ash)[68], const float (*Bsh)[68],
                                         int cw, int ty, int tx, float (&acc)[4][4]){
  #pragma unroll 8
  for (int j = 0; j < cw; j++){
    float4 av = *(const float4*)&Ash[j][ty*4];
    float4 bv = *(const float4*)&Bsh[j][tx*4];
    acc[0][0] += av.x*bv.x; acc[0][1] += av.x*bv.y; acc[0][2] += av.x*bv.z; acc[0][3] += av.x*bv.w;
    acc[1][0] += av.y*bv.x; acc[1][1] += av.y*bv.y; acc[1][2] += av.y*bv.z; acc[1][3] += av.y*bv.w;
    acc[2][0] += av.z*bv.x; acc[2][1] += av.z*bv.y; acc[2][2] += av.z*bv.z; acc[2][3] += av.z*bv.w;
    acc[3][0] += av.w*bv.x; acc[3][1] += av.w*bv.y; acc[3][2] += av.w*bv.z; acc[3][3] += av.w*bv.w;
  }
}

template<int CW>
__device__ __forceinline__ void load_tiles_T(
    const float* __restrict__ A, int lda, int mm, const unsigned char* zsh, int jba,
    const float* __restrict__ Wr, int wstr, int jbw,
    int tid, float (*Ash)[68], float (*Bsh)[68])
{
  const int QP = CW/4;
  const int NF4 = 64*QP;
  #pragma unroll
  for (int id = tid; id < NF4; id += 256){
    int row = id / QP, q = id - row*QP;
    float4 v = *(const float4*)&A[(size_t)row*lda + jba + q*4];
    if (mm == 1){ if (!zsh[row]) v = make_float4(0.f,0.f,0.f,0.f); }
    else if (mm == 2){ if (zsh[row]) v = make_float4(0.f,0.f,0.f,0.f); }
    int jj = q*4;
    Ash[jj][row]=v.x; Ash[jj+1][row]=v.y; Ash[jj+2][row]=v.z; Ash[jj+3][row]=v.w;
  }
  #pragma unroll
  for (int id = tid; id < NF4; id += 256){
    int n = id / QP, q = id - n*QP;
    float4 v = *(const float4*)&Wr[(size_t)n*wstr + jbw + q*4];
    int jj = q*4;
    Bsh[jj][n]=v.x; Bsh[jj+1][n]=v.y; Bsh[jj+2][n]=v.z; Bsh[jj+3][n]=v.w;
  }
}

// ---------------- preprocessing ----------------------------------------------
__global__ void prep_zero_kernel(){
  int idx = blockIdx.x*blockDim.x + threadIdx.x;
  if (idx < LL*BB*HH){
    g_hh[idx] = 0.f; g_c[idx] = 0.f;
    g_hhbh[idx] = __float2bfloat16(0.f);
    g_hhbl[idx] = __float2bfloat16(0.f);
  }
  if (idx == 0){ g_bar = 0u; g_bar2 = 0u; g_flag1 = 0u; g_flag2 = 0u; g_flag3 = 0u; }
}

__global__ void prep_in_kernel(const float* __restrict__ inp,
                               const float* __restrict__ boundary){
  int idx = blockIdx.x*blockDim.x + threadIdx.x;
  if (idx < TT*LL*BB){
    int b  = idx % BB;
    int kk = (idx / BB) % LL;
    int t  = idx / (BB*LL);
    const float* src = inp + (b*TT + t)*FF + kk*GG;
    bool any = false;
    #pragma unroll
    for (int j = 0; j < GG; j++){
      float v = src[j];
      bool nn = (v != v);
      any = any || (!nn);
      g_xg[idx*GG + j] = nn ? 0.f : v;
    }
    g_z[idx] = any ? 1 : 0;
  }
  if (idx < LL*TT) g_bt[idx] = (boundary[idx] > 0.5f) ? 1.f : 0.f;
}

__global__ void prep_allz_kernel(){
  int st = blockIdx.x*blockDim.x + threadIdx.x;
  if (st < TT*LL){
    unsigned char a = 1;
    for (int b = 0; b < BB; b++) a = (unsigned char)(a & g_z[st*BB + b]);
    g_allz[st] = a;
  }
}

__global__ void split4_kernel(const float* __restrict__ src,
                              __nv_bfloat16* __restrict__ hi,
                              __nv_bfloat16* __restrict__ lo, int n4){
  int i = blockIdx.x*blockDim.x + threadIdx.x;
  if (i >= n4) return;
  float4 v = ((const float4*)src)[i];
  union { __nv_bfloat16 e[4]; uint2 u; } wh, wl;
  bsplit(v.x, wh.e[0], wl.e[0]);
  bsplit(v.y, wh.e[1], wl.e[1]);
  bsplit(v.z, wh.e[2], wl.e[2]);
  bsplit(v.w, wh.e[3], wl.e[3]);
  ((uint2*)hi)[i] = wh.u;
  ((uint2*)lo)[i] = wl.u;
}

__global__ void split_xg_pad_kernel(){
  int i = blockIdx.x*blockDim.x + threadIdx.x;
  if (i >= TT*LL*BB*8) return;
  int row = i >> 3, q = i & 7;
  union { __nv_bfloat16 e[4]; uint2 u; } wh, wl;
  if (q < 4){
    float4 v = *(const float4*)&g_xg[(size_t)row*GG + q*4];
    bsplit(v.x, wh.e[0], wl.e[0]);
    bsplit(v.y, wh.e[1], wl.e[1]);
    bsplit(v.z, wh.e[2], wl.e[2]);
    bsplit(v.w, wh.e[3], wl.e[3]);
  } else { wh.u = make_uint2(0u,0u); wl.u = make_uint2(0u,0u); }
  ((uint2*)g_xgph)[i] = wh.u;
  ((uint2*)g_xgpl)[i] = wl.u;
}

__global__ void split_xw_pad_kernel(const float* __restrict__ U,
                                    const float* __restrict__ J){
  int i = blockIdx.x*blockDim.x + threadIdx.x;
  if (i >= LL*FIVEH*8) return;
  int n = i >> 3, q = i & 7;
  union { __nv_bfloat16 e[4]; uint2 u; } uh, ul, jh, jl;
  if (q < 4){
    float4 vu = *(const float4*)&U[(size_t)n*(HH+GG) + HH + q*4];
    float4 vj = *(const float4*)&J[(size_t)n*GG + q*4];
    bsplit(vu.x, uh.e[0], ul.e[0]); bsplit(vu.y, uh.e[1], ul.e[1]);
    bsplit(vu.z, uh.e[2], ul.e[2]); bsplit(vu.w, uh.e[3], ul.e[3]);
    bsplit(vj.x, jh.e[0], jl.e[0]); bsplit(vj.y, jh.e[1], jl.e[1]);
    bsplit(vj.z, jh.e[2], jl.e[2]); bsplit(vj.w, jh.e[3], jl.e[3]);
  } else {
    uh.u = ul.u = jh.u = jl.u = make_uint2(0u,0u);
  }
  ((uint2*)g_xUh)[i] = uh.u; ((uint2*)g_xUl)[i] = ul.u;
  ((uint2*)g_xJh)[i] = jh.u; ((uint2*)g_xJl)[i] = jl.u;
}

// ---------------- WMMA structural self-test ----------------------------------
__global__ void __launch_bounds__(256) selftest_wmma_kernel(){
  __shared__ __align__(32) __nv_bfloat16 sAh[64*SPAD], sAl[64*SPAD];
  __shared__ __align__(32) __nv_bfloat16 sBh[64*SPAD], sBl[64*SPAD];
  const int tid = threadIdx.x;
  {
    int row = tid >> 2, q = tid & 3;
    *(uint4*)&sAh[row*SPAD + q*8] = *(const uint4*)&g_Wbh[(size_t)row*HH + q*8];
    *(uint4*)&sAl[row*SPAD + q*8] = *(const uint4*)&g_Wbl[(size_t)row*HH + q*8];
    *(uint4*)&sBh[row*SPAD + q*8] = *(const uint4*)&g_Zbh[(size_t)row*HH + q*8];
    *(uint4*)&sBl[row*SPAD + q*8] = *(const uint4*)&g_Zbl[(size_t)row*HH + q*8];
  }
  __syncthreads();
  FragC acc[2];
  wmma::fill_fragment(acc[0], 0.f);
  wmma::fill_fragment(acc[1], 0.f);
  const int wid = tid >> 5, wm = wid & 3, wn = wid >> 2;
  #pragma unroll
  for (int s2 = 0; s2 < 2; s2++){
    int ks = s2*16;
    FragA fah, fal;
    wmma::load_matrix_sync(fah, &sAh[(wm*16)*SPAD + ks], SPAD);
    wmma::load_matrix_sync(fal, &sAl[(wm*16)*SPAD + ks], SPAD);
    #pragma unroll
    for (int ni = 0; ni < 2; ni++){
      FragB fbh, fbl;
      wmma::load_matrix_sync(fbh, &sBh[(wn*32 + ni*16)*SPAD + ks], SPAD);
      wmma::load_matrix_sync(fbl, &sBl[(wn*32 + ni*16)*SPAD + ks], SPAD);
      wmma::mma_sync(acc[ni], fah, fbh, acc[ni]);
      wmma::mma_sync(acc[ni], fal, fbh, acc[ni]);
      wmma::mma_sync(acc[ni], fah, fbl, acc[ni]);
    }
  }
  #pragma unroll
  for (int ni = 0; ni < 2; ni++)
    wmma::store_matrix_sync(&g_pp[(size_t)(wm*16)*64 + wn*32 + ni*16],
                            acc[ni], 64, wmma::mem_row_major);
}

__global__ void verify_selftest_kernel(){
  int idx = blockIdx.x*blockDim.x + threadIdx.x;
  if (idx >= 4096) return;
  int r = idx >> 6, c = idx & 63;
  float ref = 0.f;
  for (int j = 0; j < 32; j++){
    float a = __bfloat162float(g_Wbh[(size_t)r*HH + j]) + __bfloat162float(g_Wbl[(size_t)r*HH + j]);
    float b = __bfloat162float(g_Zbh[(size_t)c*HH + j]) + __bfloat162float(g_Zbl[(size_t)c*HH + j]);
    ref += a*b;
  }
  float got = g_pp[(size_t)r*64 + c];
  float d = fabsf(got - ref);
  if (!(d <= 1e-5f + 1e-3f*fabsf(ref))) atomicExch(&g_flag3, 1u);
}

// ---------------- grid barriers ----------------------------------------------
__device__ __forceinline__ void gbar_c(unsigned int tgt, unsigned int* ctr){
  __syncthreads();
  if (threadIdx.x == 0){
    __threadfence();
    atomicAdd(ctr, 1u);
    while (*((volatile unsigned int*)ctr) < tgt) __nanosleep(32);
  }
  __syncthreads();
  __threadfence();
}

// ---------------- persistent recurrence: hybrid WMMA + fp32-sg ---------------
struct CD2 { const __nv_bfloat16 *ah, *al, *bh, *bl; int astr, wstr, mm; };

__global__ void __launch_bounds__(256,1) recur_kernel(
    const float* __restrict__ W, const float* __restrict__ Z,
    const float* __restrict__ U, const float* __restrict__ V,
    const float* __restrict__ J, const float* __restrict__ bvec)
{
  if (g_flag3 != 0u) return;    // structural self-test failed -> fp32 fallback
  __shared__ __align__(32) unsigned char shb[20480];
  __shared__ float red[256];
  __shared__ float sflag[2];
  __shared__ unsigned char zsh[64];

  __nv_bfloat16* sAh = (__nv_bfloat16*)shb;
  __nv_bfloat16* sAl = (__nv_bfloat16*)(shb + 5120);
  __nv_bfloat16* sBh = (__nv_bfloat16*)(shb + 10240);
  __nv_bfloat16* sBl = (__nv_bfloat16*)(shb + 15360);
  float (*fAsh)[68] = (float(*)[68])shb;
  float (*fBsh)[68] = (float(*)[68])(shb + 8704);

  const int tid = threadIdx.x;
  const int cta = blockIdx.x;
  unsigned int tgt = 0;

  for (int st = 0; st < TT*LL; st++){
    const int t = st >> 2, k = st & 3;

    // ---- flags (identical reduction on every CTA) + margin guard ----
    float v = (t > 0 && tid < NREC) ? g_part[(st-LL)*NREC + tid] : 0.f;
    red[tid] = v; __syncthreads();
    #pragma unroll
    for (int s = 128; s > 0; s >>= 1){ if (tid < s) red[tid] += red[tid+s]; __syncthreads(); }
    if (tid == 0){
      float s0 = red[0];
      sflag[0] = (t == 0) ? g_bt[k*TT] : ((s0 > 16384.f) ? 1.f : 0.f);
      // consumed GEMM-mode sums near the threshold are unsafe under bf16 h drift
      if (t > 0 && s0 != 16384.f && fabsf(s0 - 16384.f) < 0.05f) atomicExch(&g_flag3, 1u);
    }
    __syncthreads();
    v = (k > 0 && tid < NREC) ? g_part[(st-1)*NREC + tid] : 0.f;
    red[tid] = v; __syncthreads();
    #pragma unroll
    for (int s = 128; s > 0; s >>= 1){ if (tid < s) red[tid] += red[tid+s]; __syncthreads(); }
    if (tid == 0){
      float s1 = red[0];
      sflag[1] = (k == 0) ? g_bt[t] : ((s1 > 16384.f) ? 1.f : 0.f);
      if (k > 0 && s1 != 16384.f && fabsf(s1 - 16384.f) < 0.05f) atomicExch(&g_flag3, 1u);
    }
    if (tid < 64) zsh[tid] = g_z[st*BB + tid];
    __syncthreads();

    const bool p = sflag[0] >= 0.5f, l = sflag[1] >= 0.5f;
    const int mode = (!p && l) ? 1 : ((p && !l) ? 2 : ((p && l) ? 3 : 4));
    const float* bk = bvec + k*FIVEH;
    const int e = cta*256 + tid, eb = e >> 9, eh = e & 511;
    const size_t dsth = ((size_t)((t+1)*LL + k)*BB + eb)*HH + eh;
    const size_t srch = ((size_t)(t*LL + k)*BB + eb)*HH + eh;

    if (mode == 4){
      float o  = sigf(bk[3*HH + eh]);
      float cp = g_c[(k*BB + eb)*HH + eh];
      float hn = o * tanhf(cp);
      g_hh[dsth] = hn;
      __nv_bfloat16 hi, lo; bsplit(hn, hi, lo);
      g_hhbh[dsth] = hi; g_hhbl[dsth] = lo;
      float sgv = clip01((bk[4*HH + eh] + 1.f)*0.5f);
      red[tid] = sgv; __syncthreads();
      #pragma unroll
      for (int s = 128; s > 0; s >>= 1){ if (tid < s) red[tid] += red[tid+s]; __syncthreads(); }
      if (tid == 0) g_part[st*NREC + cta] = red[0];
      tgt += NREC; gbar_c(tgt, &g_bar);
      continue;
    }

    const int ng = (mode == 1) ? 4 : 3;
    const int ngw = ng - 1;            // WMMA groups (f,g,i or g,i)
    const bool az = (g_allz[st] != 0);
    const int kn = (k+1 < LL) ? k+1 : LL-1;

    if (cta < ngw*32){
      // ---------- WMMA path: groups excluding sg ----------
      const int split = cta / (ngw*8), ntile = cta - split*(ngw*8);
      const int n0 = ntile*64, loc = n0 >> 9, h0 = n0 & 511;
      const int g = (mode == 1) ? loc : (loc + 1);
      const int wr0 = g*HH + h0;
      const int jb = split*128;

      CD2 cd[13]; int nc = 0;
      {
        const int km = (mode == 1) ? k : kn;
        const __nv_bfloat16* ah = g_hhbh + ((size_t)(t*LL + km)*BB)*HH;
        const __nv_bfloat16* al = g_hhbl + ((size_t)(t*LL + km)*BB)*HH;
        const __nv_bfloat16* bh = ((mode == 1) ? g_Wbh : g_Zbh) + ((size_t)k*FIVEH + wr0)*HH;
        const __nv_bfloat16* bl = ((mode == 1) ? g_Wbl : g_Zbl) + ((size_t)k*FIVEH + wr0)*HH;
        #pragma unroll
        for (int c4 = 0; c4 < 4; c4++)
          cd[nc++] = CD2{ah + jb + c4*32, al + jb + c4*32,
                         bh + jb + c4*32, bl + jb + c4*32, HH, HH, 0};
      }
      if (mode != 2 && k > 0){
        const __nv_bfloat16* ah = g_hhbh + ((size_t)((t+1)*LL + (k-1))*BB)*HH;
        const __nv_bfloat16* al = g_hhbl + ((size_t)((t+1)*LL + (k-1))*BB)*HH;
        {
          const __nv_bfloat16* bh = g_Ubh + ((size_t)k*FIVEH + wr0)*(HH+GG);
          const __nv_bfloat16* bl = g_Ubl + ((size_t)k*FIVEH + wr0)*(HH+GG);
          const int mm = az ? 0 : 1;
          #pragma unroll
          for (int c4 = 0; c4 < 4; c4++)
            cd[nc++] = CD2{ah + jb + c4*32, al + jb + c4*32,
                           bh + jb + c4*32, bl + jb + c4*32, HH, HH+GG, mm};
        }
        if (!az){
          const __nv_bfloat16* bh = g_Vbh + ((size_t)k*FIVEH + wr0)*HH;
          const __nv_bfloat16* bl = g_Vbl + ((size_t)k*FIVEH + wr0)*HH;
          #pragma unroll
          for (int c4 = 0; c4 < 4; c4++)
            cd[nc++] = CD2{ah + jb + c4*32, al + jb + c4*32,
                           bh + jb + c4*32, bl + jb + c4*32, HH, HH, 2};
        }
      }
      if (split == 0){
        const __nv_bfloat16* bh = ((mode != 2) ? g_xUh : g_xJh) + ((size_t)k*FIVEH + wr0)*32;
        const __nv_bfloat16* bl = ((mode != 2) ? g_xUl : g_xJl) + ((size_t)k*FIVEH + wr0)*32;
        cd[nc++] = CD2{g_xgph + (size_t)st*BB*32, g_xgpl + (size_t)st*BB*32,
                       bh, bl, 32, 32, 0};
      }

      FragC acc[2];
      wmma::fill_fragment(acc[0], 0.f);
      wmma::fill_fragment(acc[1], 0.f);
      const int wid = tid >> 5, wm = wid & 3, wn = wid >> 2;
      const uint4 z4 = make_uint4(0u,0u,0u,0u);

      for (int i = 0; i < nc; i++){
        const CD2 d = cd[i];
        {
          int row = tid >> 2, q = tid & 3;
          bool kill = (d.mm == 1 && !zsh[row]) || (d.mm == 2 && zsh[row]);
          uint4 vah = *(const uint4*)&d.ah[(size_t)row*d.astr + q*8];
          uint4 val = *(const uint4*)&d.al[(size_t)row*d.astr + q*8];
          if (kill){ vah = z4; val = z4; }
          *(uint4*)&sAh[row*SPAD + q*8] = vah;
          *(uint4*)&sAl[row*SPAD + q*8] = val;
          *(uint4*)&sBh[row*SPAD + q*8] = *(const uint4*)&d.bh[(size_t)row*d.wstr + q*8];
          *(uint4*)&sBl[row*SPAD + q*8] = *(const uint4*)&d.bl[(size_t)row*d.wstr + q*8];
        }
        __syncthreads();
        #pragma unroll
        for (int s2 = 0; s2 < 2; s2++){
          int ks = s2*16;
          FragA fah, fal;
          wmma::load_matrix_sync(fah, &sAh[(wm*16)*SPAD + ks], SPAD);
          wmma::load_matrix_sync(fal, &sAl[(wm*16)*SPAD + ks], SPAD);
          #pragma unroll
          for (int ni = 0; ni < 2; ni++){
            FragB fbh, fbl;
            wmma::load_matrix_sync(fbh, &sBh[(wn*32 + ni*16)*SPAD + ks], SPAD);
            wmma::load_matrix_sync(fbl, &sBl[(wn*32 + ni*16)*SPAD + ks], SPAD);
            wmma::mma_sync(acc[ni], fah, fbh, acc[ni]);
            wmma::mma_sync(acc[ni], fal, fbh, acc[ni]);
            wmma::mma_sync(acc[ni], fah, fbl, acc[ni]);
          }
        }
        __syncthreads();
      }
      #pragma unroll
      for (int ni = 0; ni < 2; ni++)
        wmma::store_matrix_sync(&g_pp[((size_t)split*BB + wm*16)*(4*HH) + n0 + wn*32 + ni*16],
                                acc[ni], 4*HH, wmma::mem_row_major);
    } else if (cta < ngw*32 + 32){
      // ---------- fp32 SIMT path: sg group (feeds the threshold) ----------
      const int cs = cta - ngw*32;
      const int split = cs >> 3, h0 = (cs & 7)*64;
      const size_t wr0 = (size_t)(4*HH + h0);
      const int colbase = ngw*512 + h0;
      const int jb = split*128;
      const int tx = tid & 15, ty = tid >> 4;
      float acc[4][4] = {{0.f,0.f,0.f,0.f},{0.f,0.f,0.f,0.f},{0.f,0.f,0.f,0.f},{0.f,0.f,0.f,0.f}};

      const float* bA[3]; const float* bW[3]; int bws[3]; int bmm[3]; int nb = 0;
      {
        const int km = (mode == 1) ? k : kn;
        bA[nb] = g_hh + ((size_t)(t*LL + km)*BB)*HH;
        bW[nb] = ((mode == 1) ? W : Z) + (size_t)k*FIVEH*HH + wr0*HH;
        bws[nb] = HH; bmm[nb] = 0; nb++;
      }
      if (mode != 2 && k > 0){
        const float* hlow = g_hh + ((size_t)((t+1)*LL + (k-1))*BB)*HH;
        bA[nb] = hlow; bW[nb] = U + (size_t)k*FIVEH*(HH+GG) + wr0*(HH+GG);
        bws[nb] = HH+GG; bmm[nb] = az ? 0 : 1; nb++;
        if (!az){
          bA[nb] = hlow; bW[nb] = V + (size_t)k*FIVEH*HH + wr0*HH;
          bws[nb] = HH; bmm[nb] = 2; nb++;
        }
      }
      for (int bi = 0; bi < nb; bi++){
        const float* A = bA[bi]; const float* Wr = bW[bi];
        const int ws = bws[bi], mm = bmm[bi];
        for (int j0 = 0; j0 < 128; j0 += 32){
          load_tiles_T<32>(A, HH, mm, zsh, jb + j0, Wr, ws, jb + j0, tid, fAsh, fBsh);
          __syncthreads();
          mm_inner(fAsh, fBsh, 32, ty, tx, acc);
          __syncthreads();
        }
      }
      if (split == 0){
        const float* A = g_xg + (size_t)st*BB*GG;
        const float* Wr; int ws, jbw;
        if (mode != 2){ Wr = U + (size_t)k*FIVEH*(HH+GG) + wr0*(HH+GG); ws = HH+GG; jbw = HH; }
        else          { Wr = J + (size_t)k*FIVEH*GG + wr0*GG;           ws = GG;    jbw = 0;  }
        load_tiles_T<16>(A, GG, 0, zsh, 0, Wr, ws, jbw, tid, fAsh, fBsh);
        __syncthreads();
        mm_inner(fAsh, fBsh, 16, ty, tx, acc);
        __syncthreads();
      }
      #pragma unroll
      for (int r = 0; r < 4; r++){
        float4 o = make_float4(acc[r][0], acc[r][1], acc[r][2], acc[r][3]);
        *(float4*)&g_pp[((size_t)split*BB + ty*4 + r)*(4*HH) + colbase + tx*4] = o;
      }
    }
    tgt += NREC; gbar_c(tgt, &g_bar);

    {
      const size_t pb = (size_t)eb*(4*HH) + eh;
      const size_t sp = (size_t)BB*4*HH;
      float a0 = ((g_pp[pb]      + g_pp[sp + pb])      + g_pp[2*sp + pb])      + g_pp[3*sp + pb];
      float a1 = ((g_pp[pb+HH]   + g_pp[sp + pb+HH])   + g_pp[2*sp + pb+HH])   + g_pp[3*sp + pb+HH];
      float a2 = ((g_pp[pb+2*HH] + g_pp[sp + pb+2*HH]) + g_pp[2*sp + pb+2*HH]) + g_pp[3*sp + pb+2*HH];
      float a3 = 0.f;
      if (ng == 4)
        a3 = ((g_pp[pb+3*HH] + g_pp[sp + pb+3*HH]) + g_pp[2*sp + pb+3*HH]) + g_pp[3*sp + pb+3*HH];

      float cp = g_c[(k*BB + eb)*HH + eh];
      float cn, ps;
      if (mode == 1){
        float f  = sigf (a0 + bk[eh]);
        float gg = tanhf(a1 + bk[HH + eh]);
        float ii = sigf (a2 + bk[2*HH + eh]);
        ps = a3 + bk[4*HH + eh];
        cn = f*cp + ii*gg;
      } else {
        float gg = tanhf(a0 + bk[HH + eh]);
        float ii = sigf (a1 + bk[2*HH + eh]);
        ps = a2 + bk[4*HH + eh];
        cn = ii*gg;
      }
      g_c[(k*BB + eb)*HH + eh] = cn;
      g_hh[dsth]   = g_hh[srch];
      g_hhbh[dsth] = g_hhbh[srch];
      g_hhbl[dsth] = g_hhbl[srch];
      float sgv = clip01((ps + 1.f)*0.5f);
      red[tid] = sgv; __syncthreads();
      #pragma unroll
      for (int s = 128; s > 0; s >>= 1){ if (tid < s) red[tid] += red[tid+s]; __syncthreads(); }
      if (tid == 0) g_part[st*NREC + cta] = red[0];
    }
    tgt += NREC; gbar_c(tgt, &g_bar);
  }
}

// ---------------- NaN insurance + fp32 fallback ------------------------------
__global__ void check_h_kernel(){
  if (g_flag3 != 0u) return;
  size_t i = ((size_t)blockIdx.x*blockDim.x + threadIdx.x)*4;
  const size_t n = (size_t)(TT+1)*LL*BB*HH;
  const size_t stride = (size_t)gridDim.x*blockDim.x*4;
  for (size_t j = i; j < n; j += stride){
    float4 v = *(const float4*)&g_hh[j];
    if (v.x != v.x || v.y != v.y || v.z != v.z || v.w != v.w){ g_flag3 = 1u; return; }
  }
}

__global__ void rezero_c_kernel(){
  if (g_flag3 == 0u) return;
  int idx = blockIdx.x*blockDim.x + threadIdx.x;
  if (idx < LL*BB*HH){
    g_c[idx] = 0.f;
    g_hh[idx] = 0.f;
  }
}

__global__ void __launch_bounds__(256,1) recur_f32_kernel(
    const float* __restrict__ W, const float* __restrict__ Z,
    const float* __restrict__ U, const float* __restrict__ V,
    const float* __restrict__ J, const float* __restrict__ bvec)
{
  if (g_flag3 == 0u) return;
  __shared__ float Ash[32][68];
  __shared__ float Bsh[32][68];
  __shared__ float red[256];
  __shared__ float sflag[2];
  __shared__ unsigned char zsh[64];

  const int tid = threadIdx.x;
  const int cta = blockIdx.x;
  const int tx = tid & 15, ty = tid >> 4;
  unsigned int tgt = 0;

  for (int st = 0; st < TT*LL; st++){
    const int t = st >> 2, k = st & 3;

    float v = (t > 0 && tid < NREC) ? g_part[(st-LL)*NREC + tid] : 0.f;
    red[tid] = v; __syncthreads();
    #pragma unroll
    for (int s = 128; s > 0; s >>= 1){ if (tid < s) red[tid] += red[tid+s]; __syncthreads(); }
    if (tid == 0) sflag[0] = (t == 0) ? g_bt[k*TT] : ((red[0] > 16384.f) ? 1.f : 0.f);
    __syncthreads();
    v = (k > 0 && tid < NREC) ? g_part[(st-1)*NREC + tid] : 0.f;
    red[tid] = v; __syncthreads();
    #pragma unroll
    for (int s = 128; s > 0; s >>= 1){ if (tid < s) red[tid] += red[tid+s]; __syncthreads(); }
    if (tid == 0) sflag[1] = (k == 0) ? g_bt[t] : ((red[0] > 16384.f) ? 1.f : 0.f);
    if (tid < 64) zsh[tid] = g_z[st*BB + tid];
    __syncthreads();

    const bool p = sflag[0] >= 0.5f, l = sflag[1] >= 0.5f;
    const int mode = (!p && l) ? 1 : ((p && !l) ? 2 : ((p && l) ? 3 : 4));
    const float* bk = bvec + k*FIVEH;
    const int e = cta*256 + tid, eb = e >> 9, eh = e & 511;

    if (mode == 4){
      float o  = sigf(bk[3*HH + eh]);
      float cp = g_c[(k*BB + eb)*HH + eh];
      g_hh[((size_t)((t+1)*LL + k)*BB + eb)*HH + eh] = o * tanhf(cp);
      float sgv = clip01((bk[4*HH + eh] + 1.f)*0.5f);
      red[tid] = sgv; __syncthreads();
      #pragma unroll
      for (int s = 128; s > 0; s >>= 1){ if (tid < s) red[tid] += red[tid+s]; __syncthreads(); }
      if (tid == 0) g_part[st*NREC + cta] = red[0];
      tgt += NREC; gbar_c(tgt, &g_bar2);
      continue;
    }

    const int ng = (mode == 1) ? 4 : 3;
    const int nT = ng*8;
    const bool az = (g_allz[st] != 0);

    if (cta < nT*4){
      const int split = cta / nT, ntile = cta - split*nT;
      const int n0 = ntile*64, loc = n0 >> 9, h0 = n0 & 511;
      const int g = (mode == 1) ? ((loc == 3) ? 4 : loc)
                                : ((loc == 0) ? 1 : ((loc == 1) ? 2 : 4));
      const size_t wr0 = (size_t)(g*HH + h0);
      const int jb = split*128;
      float acc[4][4] = {{0.f,0.f,0.f,0.f},{0.f,0.f,0.f,0.f},{0.f,0.f,0.f,0.f},{0.f,0.f,0.f,0.f}};

      const float* bA[3]; const float* bW[3]; int bws[3]; int bmm[3]; int nb = 0;
      {
        const int km = (mode == 1) ? k : ((k+1 < LL) ? k+1 : LL-1);
        bA[nb] = g_hh + ((size_t)(t*LL + km)*BB)*HH;
        bW[nb] = ((mode == 1) ? W : Z) + (size_t)k*FIVEH*HH + wr0*HH;
        bws[nb] = HH; bmm[nb] = 0; nb++;
      }
      if (mode != 2 && k > 0){
        const float* hlow = g_hh + ((size_t)((t+1)*LL + (k-1))*BB)*HH;
        bA[nb] = hlow; bW[nb] = U + (size_t)k*FIVEH*(HH+GG) + wr0*(HH+GG);
        bws[nb] = HH+GG; bmm[nb] = az ? 0 : 1; nb++;
        if (!az){
          bA[nb] = hlow; bW[nb] = V + (size_t)k*FIVEH*HH + wr0*HH;
          bws[nb] = HH; bmm[nb] = 2; nb++;
        }
      }
      for (int bi = 0; bi < nb; bi++){
        const float* A = bA[bi]; const float* Wr = bW[bi];
        const int ws = bws[bi], mm = bmm[bi];
        for (int j0 = 0; j0 < 128; j0 += 32){
          load_tiles_T<32>(A, HH, mm, zsh, jb + j0, Wr, ws, jb + j0, tid, Ash, Bsh);
          __syncthreads();
          mm_inner(Ash, Bsh, 32, ty, tx, acc);
          __syncthreads();
        }
      }
      if (split == 0){
        const float* A = g_xg + (size_t)st*BB*GG;
        const float* Wr; int ws, jbw;
        if (mode != 2){ Wr = U + (size_t)k*FIVEH*(HH+GG) + wr0*(HH+GG); ws = HH+GG; jbw = HH; }
        else          { Wr = J + (size_t)k*FIVEH*GG + wr0*GG;           ws = GG;    jbw = 0;  }
        load_tiles_T<16>(A, GG, 0, zsh, 0, Wr, ws, jbw, tid, Ash, Bsh);
        __syncthreads();
        mm_inner(Ash, Bsh, 16, ty, tx, acc);
        __syncthreads();
      }
      #pragma unroll
      for (int r = 0; r < 4; r++){
        float4 o = make_float4(acc[r][0], acc[r][1], acc[r][2], acc[r][3]);
        *(float4*)&g_pp[((size_t)split*BB + ty*4 + r)*(4*HH) + n0 + tx*4] = o;
      }
    }
    tgt += NREC; gbar_c(tgt, &g_bar2);

    {
      const size_t pb = (size_t)eb*(4*HH) + eh;
      const size_t sp = (size_t)BB*4*HH;
      float a0 = ((g_pp[pb]      + g_pp[sp + pb])      + g_pp[2*sp + pb])      + g_pp[3*sp + pb];
      float a1 = ((g_pp[pb+HH]   + g_pp[sp + pb+HH])   + g_pp[2*sp + pb+HH])   + g_pp[3*sp + pb+HH];
      float a2 = ((g_pp[pb+2*HH] + g_pp[sp + pb+2*HH]) + g_pp[2*sp + pb+2*HH]) + g_pp[3*sp + pb+2*HH];
      float a3 = 0.f;
      if (ng == 4)
        a3 = ((g_pp[pb+3*HH] + g_pp[sp + pb+3*HH]) + g_pp[2*sp + pb+3*HH]) + g_pp[3*sp + pb+3*HH];

      float cp = g_c[(k*BB + eb)*HH + eh];
      float cn, ps;
      if (mode == 1){
        float f  = sigf (a0 + bk[eh]);
        float gg = tanhf(a1 + bk[HH + eh]);
        float ii = sigf (a2 + bk[2*HH + eh]);
        ps = a3 + bk[4*HH + eh];
        cn = f*cp + ii*gg;
      } else {
        float gg = tanhf(a0 + bk[HH + eh]);
        float ii = sigf (a1 + bk[2*HH + eh]);
        ps = a2 + bk[4*HH + eh];
        cn = ii*gg;
      }
      g_c[(k*BB + eb)*HH + eh] = cn;
      g_hh[((size_t)((t+1)*LL + k)*BB + eb)*HH + eh] =
          g_hh[((size_t)(t*LL + k)*BB + eb)*HH + eh];
      float sgv = clip01((ps + 1.f)*0.5f);
      red[tid] = sgv; __syncthreads();
      #pragma unroll
      for (int s = 128; s > 0; s >>= 1){ if (tid < s) red[tid] += red[tid+s]; __syncthreads(); }
      if (tid == 0) g_part[st*NREC + cta] = red[0];
    }
    tgt += NREC; gbar_c(tgt, &g_bar2);
  }
}

// ---------------- bf16 split conversions (excitation) ------------------------
__global__ void conv_hcat_kernel(){
  int idx = blockIdx.x*blockDim.x + threadIdx.x;
  if (idx >= MTOT*512) return;
  int m = idx >> 9, f4 = (idx & 511);
  int f = f4*4;
  int b = m >> 7, t = m & 127;
  int kf = f >> 9, hf = f & 511;
  float4 v = *(const float4*)&g_hh[(((size_t)(t+1)*LL + kf)*BB + b)*HH + hf];
  union { __nv_bfloat16 e[4]; uint2 u; } wh, wl;
  bsplit(v.x, wh.e[0], wl.e[0]);
  bsplit(v.y, wh.e[1], wl.e[1]);
  bsplit(v.z, wh.e[2], wl.e[2]);
  bsplit(v.w, wh.e[3], wl.e[3]);
  *(uint2*)&g_Ahi[(size_t)m*2048 + f] = wh.u;
  *(uint2*)&g_Alo[(size_t)m*2048 + f] = wl.u;
}

__global__ void trans_split_kernel(const float* __restrict__ src,
                                   __nv_bfloat16* __restrict__ dhi,
                                   __nv_bfloat16* __restrict__ dlo,
                                   int R, int C){
  __shared__ float tl[32][33];
  const int z = blockIdx.z;
  const float* s = src + (size_t)z*R*C;
  __nv_bfloat16* oh = dhi + (size_t)z*R*C;
  __nv_bfloat16* ol = dlo + (size_t)z*R*C;
  int r0 = blockIdx.x*32, c0 = blockIdx.y*32;
  int tx = threadIdx.x, ty = threadIdx.y;
  #pragma unroll
  for (int i = 0; i < 4; i++)
    tl[ty + 8*i][tx] = s[(size_t)(r0 + ty + 8*i)*C + c0 + tx];
  __syncthreads();
  #pragma unroll
  for (int i = 0; i < 4; i++){
    float v = tl[tx][ty + 8*i];
    __nv_bfloat16 hi, lo; bsplit(v, hi, lo);
    size_t o = (size_t)(c0 + ty + 8*i)*R + r0 + tx;
    oh[o] = hi; ol[o] = lo;
  }
}

// ---------------- excitation: WMMA (proven R10) ------------------------------
__global__ void __launch_bounds__(256) e1_wmma_kernel(){
  __shared__ __align__(32) __nv_bfloat16 smbuf[4*128*SPAD];
  const int n0 = blockIdx.x*128, m0 = blockIdx.y*128;
  FragC acc[2][4];
  #pragma unroll
  for (int mi = 0; mi < 2; mi++)
    #pragma unroll
    for (int ni = 0; ni < 4; ni++) wmma::fill_fragment(acc[mi][ni], 0.f);

  wmma_core(smbuf,
            g_Ahi + (size_t)m0*2048, g_Alo + (size_t)m0*2048, 2048,
            g_QThi + (size_t)n0*2048, g_QTlo + (size_t)n0*2048, 2048,
            2048, acc);

  float* swp = (float*)smbuf;
  const int tid = threadIdx.x, lane = tid & 31, wid = tid >> 5;
  const int wm = wid & 3, wn = wid >> 2;
  const int kq = n0 >> 9, h0 = n0 & 511;
  float* wp = swp + wid*384;
  #pragma unroll
  for (int mi = 0; mi < 2; mi++){
    #pragma unroll
    for (int ni = 0; ni < 4; ni++){
      wmma::store_matrix_sync(wp, acc[mi][ni], 24, wmma::mem_row_major);
      __syncwarp();
      int r0 = m0 + wm*32 + mi*16;
      int c0 = h0 + wn*64 + ni*16;
      #pragma unroll
      for (int e = 0; e < 8; e++){
        int idx2 = e*32 + lane;
        int r = idx2 >> 4, c = idx2 & 15;
        float vv = sigf(wp[r*24 + c]);
        __nv_bfloat16 hi, lo; bsplit(vv, hi, lo);
        size_t o = ((size_t)kq*MTOT + r0 + r)*HH + c0 + c;
        g_R1hi[o] = hi; g_R1lo[o] = lo;
      }
      __syncwarp();
    }
  }
}

__global__ void __launch_bounds__(256) e2_wmma_kernel(){
  __shared__ __align__(32) __nv_bfloat16 smbuf[4*128*SPAD];
  const int n0 = blockIdx.x*128, m0 = blockIdx.y*128, kq = blockIdx.z;
  FragC acc[2][4];
  #pragma unroll
  for (int mi = 0; mi < 2; mi++)
    #pragma unroll
    for (int ni = 0; ni < 4; ni++) wmma::fill_fragment(acc[mi][ni], 0.f);

  wmma_core(smbuf,
            g_R1hi + ((size_t)kq*MTOT + m0)*HH, g_R1lo + ((size_t)kq*MTOT + m0)*HH, 512,
            g_RmThi + ((size_t)kq*HH + n0)*HH,  g_RmTlo + ((size_t)kq*HH + n0)*HH,  512,
            512, acc);

  const int wid = threadIdx.x >> 5;
  const int wm = wid & 3, wn = wid >> 2;
  #pragma unroll
  for (int mi = 0; mi < 2; mi++){
    #pragma unroll
    for (int ni = 0; ni < 4; ni++){
      int r0 = m0 + wm*32 + mi*16;
      int c0 = n0 + wn*64 + ni*16;
      wmma::store_matrix_sync(&g_mul1[((size_t)kq*MTOT + r0)*HH + c0],
                              acc[mi][ni], HH, wmma::mem_row_major);
    }
  }
}

// ---------------- verifiers + SIMT fallbacks ---------------------------------
__global__ void verify_e1_kernel(const float* __restrict__ Q){
  int s = blockIdx.x*blockDim.x + threadIdx.x;
  int m = (s*5) & 8191;
  int c = (s*131 + 7) & 2047;
  int kq = c >> 9, h = c & 511;
  int b = m >> 7, t = m & 127;
  float ref = 0.f;
  for (int f = 0; f < 2048; f++){
    int kf = f >> 9, hf = f & 511;
    float a = g_hh[(((size_t)(t+1)*LL + kf)*BB + b)*HH + hf];
    ref += a * Q[((size_t)kq*2048 + f)*512 + h];
  }
  float want = sigf(ref);
  size_t o = ((size_t)kq*MTOT + m)*HH + h;
  float got = __bfloat162float(g_R1hi[o]) + __bfloat162float(g_R1lo[o]);
  float d = fabsf(got - want);
  if (!(d <= 2e-3f)) atomicExch(&g_flag1, 1u);
}

__global__ void __launch_bounds__(256) e1_fb_kernel(const float* __restrict__ Q){
  if (g_flag1 == 0u) return;
  __shared__ float Ash[32][68];
  __shared__ float Bsh[32][68];
  const int tid = threadIdx.x, tx = tid & 15, ty = tid >> 4;
  const int n0 = blockIdx.x*64, m0 = blockIdx.y*64;
  const int kq = n0 >> 9, nh0 = n0 & 511;
  const int bB = m0 >> 7, t0 = m0 & 127;
  float acc[4][4] = {{0.f,0.f,0.f,0.f},{0.f,0.f,0.f,0.f},{0.f,0.f,0.f,0.f},{0.f,0.f,0.f,0.f}};
  for (int f0 = 0; f0 < LL*HH; f0 += 32){
    const int kf = f0 >> 9, hf = f0 & 511;
    const float* abase = g_hh + ((size_t)(t0+1)*LL + kf)*BB*HH + (size_t)bB*HH + hf;
    #pragma unroll
    for (int id = tid; id < 512; id += 256){
      int mi = id >> 3, q = id & 7;
      float4 v = *(const float4*)(abase + (size_t)mi*(LL*BB*HH) + q*4);
      int jj = q*4;
      Ash[jj][mi]=v.x; Ash[jj+1][mi]=v.y; Ash[jj+2][mi]=v.z; Ash[jj+3][mi]=v.w;
    }
    #pragma unroll
    for (int id = tid; id < 512; id += 256){
      int j = id >> 4, qn = id & 15;
      float4 v = *(const float4*)&Q[((size_t)kq*(LL*HH) + f0 + j)*HH + nh0 + qn*4];
      *(float4*)&Bsh[j][qn*4] = v;
    }
    __syncthreads();
    mm_inner(Ash, Bsh, 32, ty, tx, acc);
    __syncthreads();
  }
  #pragma unroll
  for (int r = 0; r < 4; r++){
    #pragma unroll
    for (int c = 0; c < 4; c++){
      float vv = sigf(acc[r][c]);
      __nv_bfloat16 hi, lo; bsplit(vv, hi, lo);
      size_t o = ((size_t)kq*MTOT + m0 + ty*4 + r)*HH + nh0 + tx*4 + c;
      g_R1hi[o] = hi; g_R1lo[o] = lo;
    }
  }
}

__global__ void verify_e2_kernel(const float* __restrict__ Rm){
  int s = blockIdx.x*blockDim.x + threadIdx.x;
  int m = (s*5) & 8191;
  int g = (s*131 + 7) & 511;
  int kq = s & 3;
  float ref = 0.f;
  for (int h = 0; h < 512; h++){
    size_t o = ((size_t)kq*MTOT + m)*HH + h;
    float r1 = __bfloat162float(g_R1hi[o]) + __bfloat162float(g_R1lo[o]);
    ref += r1 * Rm[((size_t)kq*512 + h)*512 + g];
  }
  float got = g_mul1[((size_t)kq*MTOT + m)*HH + g];
  float d = fabsf(got - ref);
  if (!(d <= 5e-3f)) atomicExch(&g_flag2, 1u);
}

__global__ void __launch_bounds__(256) e2_fb_kernel(const float* __restrict__ Rm){
  if (g_flag2 == 0u) return;
  __shared__ float Ash[32][68];
  __shared__ float Bsh[32][68];
  const int tid = threadIdx.x, tx = tid & 15, ty = tid >> 4;
  const int n0 = blockIdx.x*64, m0 = blockIdx.y*64, kq = blockIdx.z;
  float acc[4][4] = {{0.f,0.f,0.f,0.f},{0.f,0.f,0.f,0.f},{0.f,0.f,0.f,0.f},{0.f,0.f,0.f,0.f}};
  for (int f0 = 0; f0 < HH; f0 += 32){
    #pragma unroll
    for (int id = tid; id < 2048; id += 256){
      int mi = id >> 5, j = id & 31;
      size_t o = ((size_t)kq*MTOT + m0 + mi)*HH + f0 + j;
      Ash[j][mi] = __bfloat162float(g_R1hi[o]) + __bfloat162float(g_R1lo[o]);
    }
    #pragma unroll
    for (int id = tid; id < 512; id += 256){
      int j = id >> 4, qn = id & 15;
      float4 v = *(const float4*)&Rm[((size_t)kq*HH + f0 + j)*HH + n0 + qn*4];
      *(float4*)&Bsh[j][qn*4] = v;
    }
    __syncthreads();
    mm_inner(Ash, Bsh, 32, ty, tx, acc);
    __syncthreads();
  }
  #pragma unroll
  for (int r = 0; r < 4; r++){
    float4 o = make_float4(acc[r][0], acc[r][1], acc[r][2], acc[r][3]);
    *(float4*)&g_mul1[((size_t)kq*MTOT + m0 + ty*4 + r)*HH + n0 + tx*4] = o;
  }
}

__global__ void fuse_excited_kernel(){
  int idx = blockIdx.x*blockDim.x + threadIdx.x;
  if (idx >= MTOT*128) return;
  int m = idx >> 7, n = (idx & 127) << 2;
  int b = m >> 7, t = m & 127;
  float4 tot = make_float4(0.f, 0.f, 0.f, 0.f);
  #pragma unroll
  for (int k = 0; k < LL; k++){
    float4 mu = *(const float4*)&g_mul1[((size_t)k*MTOT + m)*HH + n];
    float4 hv = *(const float4*)&g_hh[(((size_t)(t+1)*LL + k)*BB + b)*HH + n];
    tot.x += mu.x*hv.x; tot.y += mu.y*hv.y; tot.z += mu.z*hv.z; tot.w += mu.w*hv.w;
  }
  float4 o = make_float4(fmaxf(tot.x,0.f), fmaxf(tot.y,0.f), fmaxf(tot.z,0.f), fmaxf(tot.w,0.f));
  *(float4*)&g_excited[(size_t)m*HH + n] = o;
}

__global__ void __launch_bounds__(256) e3_kernel(const float* __restrict__ Wo,
                                                 const float* __restrict__ bo,
                                                 float* __restrict__ out){
  __shared__ float Ash[32][68];
  __shared__ float Bsh[32][68];
  const int tid = threadIdx.x, tx = tid & 15, ty = tid >> 4;
  const int m0 = blockIdx.x*64;
  float acc[4][4] = {{0.f,0.f,0.f,0.f},{0.f,0.f,0.f,0.f},{0.f,0.f,0.f,0.f},{0.f,0.f,0.f,0.f}};
  for (int f0 = 0; f0 < HH; f0 += 32){
    load_tiles_T<32>(g_excited + (size_t)m0*HH, HH, 0, (const unsigned char*)g_z, f0,
                     Wo, HH, f0, tid, Ash, Bsh);
    __syncthreads();
    mm_inner(Ash, Bsh, 32, ty, tx, acc);
    __syncthreads();
  }
  #pragma unroll
  for (int r = 0; r < 4; r++){
    int n = tx*4;
    float4 o = make_float4(acc[r][0] + bo[n], acc[r][1] + bo[n+1],
                           acc[r][2] + bo[n+2], acc[r][3] + bo[n+3]);
    *(float4*)&out[(size_t)(m0 + ty*4 + r)*FF + n] = o;
  }
}

// ---------------- launch -----------------------------------------------------
extern "C" void kernel_launch(void* const* d_in, const int* in_sizes, int n_in,
                              void* d_out, int out_size) {
  const float* inp      = (const float*)d_in[0];
  const float* W        = (const float*)d_in[1];
  const float* Z        = (const float*)d_in[2];
  const float* U        = (const float*)d_in[3];
  const float* V        = (const float*)d_in[4];
  const float* J        = (const float*)d_in[5];
  const float* bvec     = (const float*)d_in[6];
  const float* boundary = (const float*)d_in[7];
  const float* Q        = (const float*)d_in[8];
  const float* Rm       = (const float*)d_in[9];
  const float* Wo       = (const float*)d_in[10];
  const float* bo       = (const float*)d_in[11];
  float* out            = (float*)d_out;

  prep_zero_kernel<<<512, 256>>>();
  prep_in_kernel<<<128, 256>>>(inp, boundary);
  prep_allz_kernel<<<2, 256>>>();
  split_xg_pad_kernel<<<(TT*LL*BB*8 + 255)/256, 256>>>();
  split_xw_pad_kernel<<<(LL*FIVEH*8 + 255)/256, 256>>>(U, J);

  const int nWZ = LL*FIVEH*HH/4;
  const int nU  = LL*FIVEH*(HH+GG)/4;
  split4_kernel<<<(nWZ + 255)/256, 256>>>(W, g_Wbh, g_Wbl, nWZ);
  split4_kernel<<<(nWZ + 255)/256, 256>>>(Z, g_Zbh, g_Zbl, nWZ);
  split4_kernel<<<(nWZ + 255)/256, 256>>>(V, g_Vbh, g_Vbl, nWZ);
  split4_kernel<<<(nU  + 255)/256, 256>>>(U, g_Ubh, g_Ubl, nU);

  trans_split_kernel<<<dim3(64, 16, 4), dim3(32, 8)>>>(Q,  g_QThi,  g_QTlo,  2048, 512);
  trans_split_kernel<<<dim3(16, 16, 4), dim3(32, 8)>>>(Rm, g_RmThi, g_RmTlo, 512,  512);

  // structural self-test of the recurrence WMMA path
  selftest_wmma_kernel<<<1, 256>>>();
  verify_selftest_kernel<<<16, 256>>>();

  recur_kernel<<<NREC, 256>>>(W, Z, U, V, J, bvec);

  // insurance: NaN in h OR failed self-test OR near-threshold margin -> fp32 recompute
  check_h_kernel<<<1024, 256>>>();
  rezero_c_kernel<<<512, 256>>>();
  recur_f32_kernel<<<NREC, 256>>>(W, Z, U, V, J, bvec);

  conv_hcat_kernel<<<(MTOT*512)/256, 256>>>();
  e1_wmma_kernel<<<dim3(16, 64), 256>>>();
  verify_e1_kernel<<<16, 256>>>(Q);
  e1_fb_kernel<<<dim3(32, 128), 256>>>(Q);
  e2_wmma_kernel<<<dim3(4, 64, 4), 256>>>();
  verify_e2_kernel<<<16, 256>>>(Rm);
  e2_fb_kernel<<<dim3(8, 128, 4), 256>>>(Rm);
  fuse_excited_kernel<<<(MTOT*128)/256, 256>>>();
  e3_kernel<<<128, 256>>>(Wo, bo, out);
}

// round 16
// speedup vs baseline: 1.7765x; 1.7765x over previous
#include <cuda_runtime.h>
#include <cuda_bf16.h>
#include <mma.h>
#include <math.h>
#include <stdint.h>

using namespace nvcuda;

#define TT 128
#define LL 4
#define BB 64
#define HH 512
#define GG 16
#define FF 64
#define NREC 128
#define FIVEH (5*HH)
#define MTOT (BB*TT)   // 8192

// ---------------- scratch (device globals; no allocations) -------------------
__device__ __align__(128) float g_hh[(size_t)(TT+1)*LL*BB*HH];
__device__ __align__(128) float g_c[LL*BB*HH];
__device__ __align__(128) float g_xg[TT*LL*BB*GG];
__device__ unsigned char g_z[TT*LL*BB];
__device__ unsigned char g_allz[TT*LL];
__device__ float g_bt[LL*TT];
__device__ __align__(128) float g_part[TT*LL*NREC];
__device__ __align__(128) float g_pp [4*BB*4*HH];
__device__ __align__(128) float g_pp2[4*BB*4*HH];
__device__ unsigned int g_bar;
__device__ unsigned int g_flag1, g_flag2;
__device__ __align__(128) float g_excited[(size_t)MTOT*HH];

// bf16 split buffers for the excitation GEMMs (proven R10)
__device__ __align__(128) __nv_bfloat16 g_Ahi[(size_t)MTOT*2048];
__device__ __align__(128) __nv_bfloat16 g_Alo[(size_t)MTOT*2048];
__device__ __align__(128) __nv_bfloat16 g_QThi[(size_t)LL*HH*2048];
__device__ __align__(128) __nv_bfloat16 g_QTlo[(size_t)LL*HH*2048];
__device__ __align__(128) __nv_bfloat16 g_R1hi[(size_t)LL*MTOT*HH];
__device__ __align__(128) __nv_bfloat16 g_R1lo[(size_t)LL*MTOT*HH];
__device__ __align__(128) __nv_bfloat16 g_RmThi[(size_t)LL*HH*HH];
__device__ __align__(128) __nv_bfloat16 g_RmTlo[(size_t)LL*HH*HH];
__device__ __align__(128) float g_mul1[(size_t)LL*MTOT*HH];

__device__ __forceinline__ float sigf(float x){ return 1.f/(1.f+expf(-x)); }
__device__ __forceinline__ float clip01(float x){ return fminf(fmaxf(x,0.f),1.f); }
__device__ __forceinline__ void bsplit(float x, __nv_bfloat16& hi, __nv_bfloat16& lo){
  hi = __float2bfloat16(x);
  lo = __float2bfloat16(x - __bfloat162float(hi));
}

// ---------------- WMMA common (excitation only) ------------------------------
#define SPAD 40

using FragA = wmma::fragment<wmma::matrix_a,16,16,16,__nv_bfloat16,wmma::row_major>;
using FragB = wmma::fragment<wmma::matrix_b,16,16,16,__nv_bfloat16,wmma::col_major>;
using FragC = wmma::fragment<wmma::accumulator,16,16,16,float>;

__device__ __forceinline__ void wmma_core(
    __nv_bfloat16* sm,
    const __nv_bfloat16* __restrict__ Ah, const __nv_bfloat16* __restrict__ Al, int lda,
    const __nv_bfloat16* __restrict__ Bh, const __nv_bfloat16* __restrict__ Bl, int ldb,
    int ktot, FragC (&acc)[2][4])
{
  __nv_bfloat16* sAh = sm;
  __nv_bfloat16* sAl = sm +   128*SPAD;
  __nv_bfloat16* sBh = sm + 2*128*SPAD;
  __nv_bfloat16* sBl = sm + 3*128*SPAD;
  const int tid = threadIdx.x, wid = tid >> 5;
  const int wm = wid & 3, wn = wid >> 2;

  for (int kc = 0; kc < ktot; kc += 32){
    #pragma unroll
    for (int id = tid; id < 512; id += 256){
      int row = id >> 2, q = id & 3;
      *(uint4*)&sAh[row*SPAD + q*8] = *(const uint4*)&Ah[(size_t)row*lda + kc + q*8];
      *(uint4*)&sAl[row*SPAD + q*8] = *(const uint4*)&Al[(size_t)row*lda + kc + q*8];
      *(uint4*)&sBh[row*SPAD + q*8] = *(const uint4*)&Bh[(size_t)row*ldb + kc + q*8];
      *(uint4*)&sBl[row*SPAD + q*8] = *(const uint4*)&Bl[(size_t)row*ldb + kc + q*8];
    }
    __syncthreads();
    #pragma unroll
    for (int ks = 0; ks < 32; ks += 16){
      FragA fah[2], fal[2];
      #pragma unroll
      for (int mi = 0; mi < 2; mi++){
        wmma::load_matrix_sync(fah[mi], &sAh[(wm*32 + mi*16)*SPAD + ks], SPAD);
        wmma::load_matrix_sync(fal[mi], &sAl[(wm*32 + mi*16)*SPAD + ks], SPAD);
      }
      #pragma unroll
      for (int ni = 0; ni < 4; ni++){
        FragB fbh, fbl;
        wmma::load_matrix_sync(fbh, &sBh[(wn*64 + ni*16)*SPAD + ks], SPAD);
        wmma::load_matrix_sync(fbl, &sBl[(wn*64 + ni*16)*SPAD + ks], SPAD);
        #pragma unroll
        for (int mi = 0; mi < 2; mi++){
          wmma::mma_sync(acc[mi][ni], fah[mi], fbh, acc[mi][ni]);
          wmma::mma_sync(acc[mi][ni], fal[mi], fbh, acc[mi][ni]);
          wmma::mma_sync(acc[mi][ni], fah[mi], fbl, acc[mi][ni]);
        }
      }
    }
    __syncthreads();
  }
}

// ---------------- fp32 SIMT GEMM helpers (bit-exact R10) ---------------------
__device__ __forceinline__ void mm_inner(const float (*Ash)[68], const float (*Bsh)[68],
                                         int cw, int ty, int tx, float (&acc)[4][4]){
  #pragma unroll 8
  for (int j = 0; j < cw; j++){
    float4 av = *(const float4*)&Ash[j][ty*4];
    float4 bv = *(const float4*)&Bsh[j][tx*4];
    acc[0][0] += av.x*bv.x; acc[0][1] += av.x*bv.y; acc[0][2] += av.x*bv.z; acc[0][3] += av.x*bv.w;
    acc[1][0] += av.y*bv.x; acc[1][1] += av.y*bv.y; acc[1][2] += av.y*bv.z; acc[1][3] += av.y*bv.w;
    acc[2][0] += av.z*bv.x; acc[2][1] += av.z*bv.y; acc[2][2] += av.z*bv.z; acc[2][3] += av.z*bv.w;
    acc[3][0] += av.w*bv.x; acc[3][1] += av.w*bv.y; acc[3][2] += av.w*bv.z; acc[3][3] += av.w*bv.w;
  }
}

template<int CW>
__device__ __forceinline__ void load_tiles_T(
    const float* __restrict__ A, int lda, int mm, const unsigned char* zsh, int jba,
    const float* __restrict__ Wr, int wstr, int jbw,
    int tid, float (*Ash)[68], float (*Bsh)[68])
{
  const int QP = CW/4;
  const int NF4 = 64*QP;
  #pragma unroll
  for (int id = tid; id < NF4; id += 256){
    int row = id / QP, q = id - row*QP;
    float4 v = *(const float4*)&A[(size_t)row*lda + jba + q*4];
    if (mm == 1){ if (!zsh[row]) v = make_float4(0.f,0.f,0.f,0.f); }
    else if (mm == 2){ if (zsh[row]) v = make_float4(0.f,0.f,0.f,0.f); }
    int jj = q*4;
    Ash[jj][row]=v.x; Ash[jj+1][row]=v.y; Ash[jj+2][row]=v.z; Ash[jj+3][row]=v.w;
  }
  #pragma unroll
  for (int id = tid; id < NF4; id += 256){
    int n = id / QP, q = id - n*QP;
    float4 v = *(const float4*)&Wr[(size_t)n*wstr + jbw + q*4];
    int jj = q*4;
    Bsh[jj][n]=v.x; Bsh[jj+1][n]=v.y; Bsh[jj+2][n]=v.z; Bsh[jj+3][n]=v.w;
  }
}

// ---------------- preprocessing ----------------------------------------------
__global__ void prep_zero_kernel(){
  int idx = blockIdx.x*blockDim.x + threadIdx.x;
  if (idx < LL*BB*HH){ g_hh[idx] = 0.f; g_c[idx] = 0.f; }
  if (idx == 0){ g_bar = 0u; g_flag1 = 0u; g_flag2 = 0u; }
}

__global__ void prep_in_kernel(const float* __restrict__ inp,
                               const float* __restrict__ boundary){
  int idx = blockIdx.x*blockDim.x + threadIdx.x;
  if (idx < TT*LL*BB){
    int b  = idx % BB;
    int kk = (idx / BB) % LL;
    int t  = idx / (BB*LL);
    const float* src = inp + (b*TT + t)*FF + kk*GG;
    bool any = false;
    #pragma unroll
    for (int j = 0; j < GG; j++){
      float v = src[j];
      bool nn = (v != v);
      any = any || (!nn);
      g_xg[idx*GG + j] = nn ? 0.f : v;
    }
    g_z[idx] = any ? 1 : 0;
  }
  if (idx < LL*TT) g_bt[idx] = (boundary[idx] > 0.5f) ? 1.f : 0.f;
}

__global__ void prep_allz_kernel(){
  int st = blockIdx.x*blockDim.x + threadIdx.x;
  if (st < TT*LL){
    unsigned char a = 1;
    for (int b = 0; b < BB; b++) a = (unsigned char)(a & g_z[st*BB + b]);
    g_allz[st] = a;
  }
}

// ---------------- grid barrier -----------------------------------------------
__device__ __forceinline__ void gbar(unsigned int tgt){
  __syncthreads();
  if (threadIdx.x == 0){
    __threadfence();
    atomicAdd(&g_bar, 1u);
    while (*((volatile unsigned int*)&g_bar) < tgt) __nanosleep(32);
  }
  __syncthreads();
  __threadfence();
}

// ---------------- recurrence GEMM job (bit-exact R10 body) -------------------
__device__ __forceinline__ void gemm_job(
    int t, int k, int mode, bool az, const unsigned char* zsh, int j, float* pp,
    const float* __restrict__ W, const float* __restrict__ Z,
    const float* __restrict__ U, const float* __restrict__ V,
    const float* __restrict__ Jm,
    int tid, int tx, int ty, float (*Ash)[68], float (*Bsh)[68])
{
  const int ng = (mode == 1) ? 4 : 3, nT = ng*8;
  const int split = j / nT, ntile = j - split*nT;
  const int n0 = ntile*64, loc = n0 >> 9, h0 = n0 & 511;
  const int g = (mode == 1) ? ((loc == 3) ? 4 : loc)
                            : ((loc == 0) ? 1 : ((loc == 1) ? 2 : 4));
  const size_t wr0 = (size_t)(g*HH + h0);
  const int jb = split*128;
  float acc[4][4] = {{0.f,0.f,0.f,0.f},{0.f,0.f,0.f,0.f},{0.f,0.f,0.f,0.f},{0.f,0.f,0.f,0.f}};

  const float* bA[3]; const float* bW[3]; int bws[3]; int bmm[3]; int nb = 0;
  {
    const int km = (mode == 1) ? k : ((k+1 < LL) ? k+1 : LL-1);
    bA[nb] = g_hh + ((size_t)(t*LL + km)*BB)*HH;
    bW[nb] = ((mode == 1) ? W : Z) + (size_t)k*FIVEH*HH + wr0*HH;
    bws[nb] = HH; bmm[nb] = 0; nb++;
  }
  if (mode != 2 && k > 0){
    const float* hlow = g_hh + ((size_t)((t+1)*LL + (k-1))*BB)*HH;
    bA[nb] = hlow; bW[nb] = U + (size_t)k*FIVEH*(HH+GG) + wr0*(HH+GG);
    bws[nb] = HH+GG; bmm[nb] = az ? 0 : 1; nb++;
    if (!az){
      bA[nb] = hlow; bW[nb] = V + (size_t)k*FIVEH*HH + wr0*HH;
      bws[nb] = HH; bmm[nb] = 2; nb++;
    }
  }
  for (int bi = 0; bi < nb; bi++){
    const float* A = bA[bi]; const float* Wr = bW[bi];
    const int ws = bws[bi], mm = bmm[bi];
    for (int j0 = 0; j0 < 128; j0 += 32){
      load_tiles_T<32>(A, HH, mm, zsh, jb + j0, Wr, ws, jb + j0, tid, Ash, Bsh);
      __syncthreads();
      mm_inner(Ash, Bsh, 32, ty, tx, acc);
      __syncthreads();
    }
  }
  if (split == 0){
    const float* A = g_xg + (size_t)(t*LL + k)*BB*GG;
    const float* Wr; int ws, jbw;
    if (mode != 2){ Wr = U + (size_t)k*FIVEH*(HH+GG) + wr0*(HH+GG); ws = HH+GG; jbw = HH; }
    else          { Wr = Jm + (size_t)k*FIVEH*GG + wr0*GG;          ws = GG;    jbw = 0;  }
    load_tiles_T<16>(A, GG, 0, zsh, 0, Wr, ws, jbw, tid, Ash, Bsh);
    __syncthreads();
    mm_inner(Ash, Bsh, 16, ty, tx, acc);
    __syncthreads();
  }
  #pragma unroll
  for (int r = 0; r < 4; r++){
    float4 o = make_float4(acc[r][0], acc[r][1], acc[r][2], acc[r][3]);
    *(float4*)&pp[((size_t)split*BB + ty*4 + r)*(4*HH) + n0 + tx*4] = o;
  }
}

// ---------------- per-stage epilogue (bit-exact R10 body) --------------------
__device__ __forceinline__ void epi_stage(
    int t, int k, int mode, const float* __restrict__ pp,
    const float* __restrict__ bvec, int tid, int cta, float* red)
{
  const float* bk = bvec + k*FIVEH;
  const int e = cta*256 + tid, eb = e >> 9, eh = e & 511;
  const size_t dsth = ((size_t)((t+1)*LL + k)*BB + eb)*HH + eh;
  const size_t srch = ((size_t)(t*LL + k)*BB + eb)*HH + eh;
  float sgv;
  if (mode == 4){
    float o  = sigf(bk[3*HH + eh]);
    float cp = g_c[(k*BB + eb)*HH + eh];
    g_hh[dsth] = o * tanhf(cp);
    sgv = clip01((bk[4*HH + eh] + 1.f)*0.5f);
  } else {
    const int ng = (mode == 1) ? 4 : 3;
    const size_t pb = (size_t)eb*(4*HH) + eh;
    const size_t sp = (size_t)BB*4*HH;
    float a0 = ((pp[pb]      + pp[sp + pb])      + pp[2*sp + pb])      + pp[3*sp + pb];
    float a1 = ((pp[pb+HH]   + pp[sp + pb+HH])   + pp[2*sp + pb+HH])   + pp[3*sp + pb+HH];
    float a2 = ((pp[pb+2*HH] + pp[sp + pb+2*HH]) + pp[2*sp + pb+2*HH]) + pp[3*sp + pb+2*HH];
    float a3 = 0.f;
    if (ng == 4)
      a3 = ((pp[pb+3*HH] + pp[sp + pb+3*HH]) + pp[2*sp + pb+3*HH]) + pp[3*sp + pb+3*HH];

    float cp = g_c[(k*BB + eb)*HH + eh];
    float cn, ps;
    if (mode == 1){
      float f  = sigf (a0 + bk[eh]);
      float gg = tanhf(a1 + bk[HH + eh]);
      float ii = sigf (a2 + bk[2*HH + eh]);
      ps = a3 + bk[4*HH + eh];
      cn = f*cp + ii*gg;
    } else {
      float gg = tanhf(a0 + bk[HH + eh]);
      float ii = sigf (a1 + bk[2*HH + eh]);
      ps = a2 + bk[4*HH + eh];
      cn = ii*gg;
    }
    g_c[(k*BB + eb)*HH + eh] = cn;
    g_hh[dsth] = g_hh[srch];
    sgv = clip01((ps + 1.f)*0.5f);
  }
  red[tid] = sgv; __syncthreads();
  #pragma unroll
  for (int s = 128; s > 0; s >>= 1){ if (tid < s) red[tid] += red[tid+s]; __syncthreads(); }
  if (tid == 0) g_part[(t*LL + k)*NREC + cta] = red[0];
  __syncthreads();
}

// ---------------- persistent recurrence: fp32, 2-stage wavefront -------------
__global__ void __launch_bounds__(256,1) recur_kernel(
    const float* __restrict__ W, const float* __restrict__ Z,
    const float* __restrict__ U, const float* __restrict__ V,
    const float* __restrict__ Jm, const float* __restrict__ bvec)
{
  __shared__ float Ash[32][68];
  __shared__ float Bsh[32][68];
  __shared__ float red[256];
  __shared__ float sfl[4];
  __shared__ unsigned char zshA[64], zshB[64];

  const int tid = threadIdx.x;
  const int cta = blockIdx.x;
  const int tx = tid & 15, ty = tid >> 4;
  unsigned int tgt = 0;

  for (int w = 0; w <= 2*(TT-1)+3; w++){       // 258 waves
    const int kA = (w & 1), kB = kA + 2;
    const int tA = (w - kA) >> 1, tB = (w - kB) >> 1;
    const bool hasA = (tA < TT);               // tA >= 0 always
    const bool hasB = (tB >= 0) && (tB < TT);
    const int stA = tA*LL + kA, stB = tB*LL + kB;

    // ---- flags (identical deterministic reductions on every CTA) ----
    if (hasA){
      float v = (tA > 0 && tid < NREC) ? g_part[(stA-LL)*NREC + tid] : 0.f;
      red[tid] = v; __syncthreads();
      #pragma unroll
      for (int s = 128; s > 0; s >>= 1){ if (tid < s) red[tid] += red[tid+s]; __syncthreads(); }
      if (tid == 0) sfl[0] = (tA == 0) ? g_bt[kA*TT] : ((red[0] > 16384.f) ? 1.f : 0.f);
      __syncthreads();
      v = (kA > 0 && tid < NREC) ? g_part[(stA-1)*NREC + tid] : 0.f;
      red[tid] = v; __syncthreads();
      #pragma unroll
      for (int s = 128; s > 0; s >>= 1){ if (tid < s) red[tid] += red[tid+s]; __syncthreads(); }
      if (tid == 0) sfl[1] = (kA == 0) ? g_bt[tA] : ((red[0] > 16384.f) ? 1.f : 0.f);
      __syncthreads();
    }
    if (hasB){
      float v = (tB > 0 && tid < NREC) ? g_part[(stB-LL)*NREC + tid] : 0.f;
      red[tid] = v; __syncthreads();
      #pragma unroll
      for (int s = 128; s > 0; s >>= 1){ if (tid < s) red[tid] += red[tid+s]; __syncthreads(); }
      if (tid == 0) sfl[2] = (tB == 0) ? g_bt[kB*TT] : ((red[0] > 16384.f) ? 1.f : 0.f);
      __syncthreads();
      v = g_part[(stB-1)*NREC + ((tid < NREC) ? tid : 0)];
      v = (tid < NREC) ? v : 0.f;                          // kB >= 2 -> always k>0 path
      red[tid] = v; __syncthreads();
      #pragma unroll
      for (int s = 128; s > 0; s >>= 1){ if (tid < s) red[tid] += red[tid+s]; __syncthreads(); }
      if (tid == 0) sfl[3] = (red[0] > 16384.f) ? 1.f : 0.f;
      __syncthreads();
    }
    if (tid < 64){
      if (hasA) zshA[tid] = g_z[stA*BB + tid];
      if (hasB) zshB[tid] = g_z[stB*BB + tid];
    }
    __syncthreads();

    int modeA = 4, modeB = 4;
    if (hasA){
      bool p = sfl[0] >= 0.5f, l = sfl[1] >= 0.5f;
      modeA = (!p && l) ? 1 : ((p && !l) ? 2 : ((p && l) ? 3 : 4));
    }
    if (hasB){
      bool p = sfl[2] >= 0.5f, l = sfl[3] >= 0.5f;
      modeB = (!p && l) ? 1 : ((p && !l) ? 2 : ((p && l) ? 3 : 4));
    }
    const bool azA = hasA && (g_allz[stA] != 0);
    const bool azB = hasB && (g_allz[stB] != 0);
    const int nJA = (hasA && modeA != 4) ? ((modeA == 1) ? 128 : 96) : 0;
    const int nJB = (hasB && modeB != 4) ? ((modeB == 1) ? 128 : 96) : 0;
    const int totJ = nJA + nJB;

    // ---- GEMM phase: jobs of both stages spread across 128 CTAs ----
    for (int gj = cta; gj < totJ; gj += NREC){
      if (gj < nJA)
        gemm_job(tA, kA, modeA, azA, zshA, gj, g_pp, W, Z, U, V, Jm, tid, tx, ty, Ash, Bsh);
      else
        gemm_job(tB, kB, modeB, azB, zshB, gj - nJA, g_pp2, W, Z, U, V, Jm, tid, tx, ty, Ash, Bsh);
    }
    if (totJ > 0){ tgt += NREC; gbar(tgt); }

    // ---- epilogues (A then B), then wave barrier ----
    if (hasA) epi_stage(tA, kA, modeA, g_pp,  bvec, tid, cta, red);
    if (hasB) epi_stage(tB, kB, modeB, g_pp2, bvec, tid, cta, red);
    tgt += NREC; gbar(tgt);
  }
}

// ---------------- bf16 split conversions (excitation) ------------------------
__global__ void conv_hcat_kernel(){
  int idx = blockIdx.x*blockDim.x + threadIdx.x;
  if (idx >= MTOT*512) return;
  int m = idx >> 9, f4 = (idx & 511);
  int f = f4*4;
  int b = m >> 7, t = m & 127;
  int kf = f >> 9, hf = f & 511;
  float4 v = *(const float4*)&g_hh[(((size_t)(t+1)*LL + kf)*BB + b)*HH + hf];
  union { __nv_bfloat16 e[4]; uint2 u; } wh, wl;
  bsplit(v.x, wh.e[0], wl.e[0]);
  bsplit(v.y, wh.e[1], wl.e[1]);
  bsplit(v.z, wh.e[2], wl.e[2]);
  bsplit(v.w, wh.e[3], wl.e[3]);
  *(uint2*)&g_Ahi[(size_t)m*2048 + f] = wh.u;
  *(uint2*)&g_Alo[(size_t)m*2048 + f] = wl.u;
}

__global__ void trans_split_kernel(const float* __restrict__ src,
                                   __nv_bfloat16* __restrict__ dhi,
                                   __nv_bfloat16* __restrict__ dlo,
                                   int R, int C){
  __shared__ float tl[32][33];
  const int z = blockIdx.z;
  const float* s = src + (size_t)z*R*C;
  __nv_bfloat16* oh = dhi + (size_t)z*R*C;
  __nv_bfloat16* ol = dlo + (size_t)z*R*C;
  int r0 = blockIdx.x*32, c0 = blockIdx.y*32;
  int tx = threadIdx.x, ty = threadIdx.y;
  #pragma unroll
  for (int i = 0; i < 4; i++)
    tl[ty + 8*i][tx] = s[(size_t)(r0 + ty + 8*i)*C + c0 + tx];
  __syncthreads();
  #pragma unroll
  for (int i = 0; i < 4; i++){
    float v = tl[tx][ty + 8*i];
    __nv_bfloat16 hi, lo; bsplit(v, hi, lo);
    size_t o = (size_t)(c0 + ty + 8*i)*R + r0 + tx;
    oh[o] = hi; ol[o] = lo;
  }
}

// ---------------- excitation: WMMA (proven R10) ------------------------------
__global__ void __launch_bounds__(256) e1_wmma_kernel(){
  __shared__ __align__(32) __nv_bfloat16 smbuf[4*128*SPAD];
  const int n0 = blockIdx.x*128, m0 = blockIdx.y*128;
  FragC acc[2][4];
  #pragma unroll
  for (int mi = 0; mi < 2; mi++)
    #pragma unroll
    for (int ni = 0; ni < 4; ni++) wmma::fill_fragment(acc[mi][ni], 0.f);

  wmma_core(smbuf,
            g_Ahi + (size_t)m0*2048, g_Alo + (size_t)m0*2048, 2048,
            g_QThi + (size_t)n0*2048, g_QTlo + (size_t)n0*2048, 2048,
            2048, acc);

  float* swp = (float*)smbuf;
  const int tid = threadIdx.x, lane = tid & 31, wid = tid >> 5;
  const int wm = wid & 3, wn = wid >> 2;
  const int kq = n0 >> 9, h0 = n0 & 511;
  float* wp = swp + wid*384;
  #pragma unroll
  for (int mi = 0; mi < 2; mi++){
    #pragma unroll
    for (int ni = 0; ni < 4; ni++){
      wmma::store_matrix_sync(wp, acc[mi][ni], 24, wmma::mem_row_major);
      __syncwarp();
      int r0 = m0 + wm*32 + mi*16;
      int c0 = h0 + wn*64 + ni*16;
      #pragma unroll
      for (int e = 0; e < 8; e++){
        int idx2 = e*32 + lane;
        int r = idx2 >> 4, c = idx2 & 15;
        float vv = sigf(wp[r*24 + c]);
        __nv_bfloat16 hi, lo; bsplit(vv, hi, lo);
        size_t o = ((size_t)kq*MTOT + r0 + r)*HH + c0 + c;
        g_R1hi[o] = hi; g_R1lo[o] = lo;
      }
      __syncwarp();
    }
  }
}

__global__ void __launch_bounds__(256) e2_wmma_kernel(){
  __shared__ __align__(32) __nv_bfloat16 smbuf[4*128*SPAD];
  const int n0 = blockIdx.x*128, m0 = blockIdx.y*128, kq = blockIdx.z;
  FragC acc[2][4];
  #pragma unroll
  for (int mi = 0; mi < 2; mi++)
    #pragma unroll
    for (int ni = 0; ni < 4; ni++) wmma::fill_fragment(acc[mi][ni], 0.f);

  wmma_core(smbuf,
            g_R1hi + ((size_t)kq*MTOT + m0)*HH, g_R1lo + ((size_t)kq*MTOT + m0)*HH, 512,
            g_RmThi + ((size_t)kq*HH + n0)*HH,  g_RmTlo + ((size_t)kq*HH + n0)*HH,  512,
            512, acc);

  const int wid = threadIdx.x >> 5;
  const int wm = wid & 3, wn = wid >> 2;
  #pragma unroll
  for (int mi = 0; mi < 2; mi++){
    #pragma unroll
    for (int ni = 0; ni < 4; ni++){
      int r0 = m0 + wm*32 + mi*16;
      int c0 = n0 + wn*64 + ni*16;
      wmma::store_matrix_sync(&g_mul1[((size_t)kq*MTOT + r0)*HH + c0],
                              acc[mi][ni], HH, wmma::mem_row_major);
    }
  }
}

// ---------------- verifiers + SIMT fallbacks (proven, silent) ----------------
__global__ void verify_e1_kernel(const float* __restrict__ Q){
  int s = blockIdx.x*blockDim.x + threadIdx.x;
  int m = (s*5) & 8191;
  int c = (s*131 + 7) & 2047;
  int kq = c >> 9, h = c & 511;
  int b = m >> 7, t = m & 127;
  float ref = 0.f;
  for (int f = 0; f < 2048; f++){
    int kf = f >> 9, hf = f & 511;
    float a = g_hh[(((size_t)(t+1)*LL + kf)*BB + b)*HH + hf];
    ref += a * Q[((size_t)kq*2048 + f)*512 + h];
  }
  float want = sigf(ref);
  size_t o = ((size_t)kq*MTOT + m)*HH + h;
  float got = __bfloat162float(g_R1hi[o]) + __bfloat162float(g_R1lo[o]);
  float d = fabsf(got - want);
  if (!(d <= 2e-3f)) atomicExch(&g_flag1, 1u);
}

__global__ void __launch_bounds__(256) e1_fb_kernel(const float* __restrict__ Q){
  if (g_flag1 == 0u) return;
  __shared__ float Ash[32][68];
  __shared__ float Bsh[32][68];
  const int tid = threadIdx.x, tx = tid & 15, ty = tid >> 4;
  const int n0 = blockIdx.x*64, m0 = blockIdx.y*64;
  const int kq = n0 >> 9, nh0 = n0 & 511;
  const int bB = m0 >> 7, t0 = m0 & 127;
  float acc[4][4] = {{0.f,0.f,0.f,0.f},{0.f,0.f,0.f,0.f},{0.f,0.f,0.f,0.f},{0.f,0.f,0.f,0.f}};
  for (int f0 = 0; f0 < LL*HH; f0 += 32){
    const int kf = f0 >> 9, hf = f0 & 511;
    const float* abase = g_hh + ((size_t)(t0+1)*LL + kf)*BB*HH + (size_t)bB*HH + hf;
    #pragma unroll
    for (int id = tid; id < 512; id += 256){
      int mi = id >> 3, q = id & 7;
      float4 v = *(const float4*)(abase + (size_t)mi*(LL*BB*HH) + q*4);
      int jj = q*4;
      Ash[jj][mi]=v.x; Ash[jj+1][mi]=v.y; Ash[jj+2][mi]=v.z; Ash[jj+3][mi]=v.w;
    }
    #pragma unroll
    for (int id = tid; id < 512; id += 256){
      int j = id >> 4, qn = id & 15;
      float4 v = *(const float4*)&Q[((size_t)kq*(LL*HH) + f0 + j)*HH + nh0 + qn*4];
      *(float4*)&Bsh[j][qn*4] = v;
    }
    __syncthreads();
    mm_inner(Ash, Bsh, 32, ty, tx, acc);
    __syncthreads();
  }
  #pragma unroll
  for (int r = 0; r < 4; r++){
    #pragma unroll
    for (int c = 0; c < 4; c++){
      float vv = sigf(acc[r][c]);
      __nv_bfloat16 hi, lo; bsplit(vv, hi, lo);
      size_t o = ((size_t)kq*MTOT + m0 + ty*4 + r)*HH + nh0 + tx*4 + c;
      g_R1hi[o] = hi; g_R1lo[o] = lo;
    }
  }
}

__global__ void verify_e2_kernel(const float* __restrict__ Rm){
  int s = blockIdx.x*blockDim.x + threadIdx.x;
  int m = (s*5) & 8191;
  int g = (s*131 + 7) & 511;
  int kq = s & 3;
  float ref = 0.f;
  for (int h = 0; h < 512; h++){
    size_t o = ((size_t)kq*MTOT + m)*HH + h;
    float r1 = __bfloat162float(g_R1hi[o]) + __bfloat162float(g_R1lo[o]);
    ref += r1 * Rm[((size_t)kq*512 + h)*512 + g];
  }
  float got = g_mul1[((size_t)kq*MTOT + m)*HH + g];
  float d = fabsf(got - ref);
  if (!(d <= 5e-3f)) atomicExch(&g_flag2, 1u);
}

__global__ void __launch_bounds__(256) e2_fb_kernel(const float* __restrict__ Rm){
  if (g_flag2 == 0u) return;
  __shared__ float Ash[32][68];
  __shared__ float Bsh[32][68];
  const int tid = threadIdx.x, tx = tid & 15, ty = tid >> 4;
  const int n0 = blockIdx.x*64, m0 = blockIdx.y*64, kq = blockIdx.z;
  float acc[4][4] = {{0.f,0.f,0.f,0.f},{0.f,0.f,0.f,0.f},{0.f,0.f,0.f,0.f},{0.f,0.f,0.f,0.f}};
  for (int f0 = 0; f0 < HH; f0 += 32){
    #pragma unroll
    for (int id = tid; id < 2048; id += 256){
      int mi = id >> 5, j = id & 31;
      size_t o = ((size_t)kq*MTOT + m0 + mi)*HH + f0 + j;
      Ash[j][mi] = __bfloat162float(g_R1hi[o]) + __bfloat162float(g_R1lo[o]);
    }
    #pragma unroll
    for (int id = tid; id < 512; id += 256){
      int j = id >> 4, qn = id & 15;
      float4 v = *(const float4*)&Rm[((size_t)kq*HH + f0 + j)*HH + n0 + qn*4];
      *(float4*)&Bsh[j][qn*4] = v;
    }
    __syncthreads();
    mm_inner(Ash, Bsh, 32, ty, tx, acc);
    __syncthreads();
  }
  #pragma unroll
  for (int r = 0; r < 4; r++){
    float4 o = make_float4(acc[r][0], acc[r][1], acc[r][2], acc[r][3]);
    *(float4*)&g_mul1[((size_t)kq*MTOT + m0 + ty*4 + r)*HH + n0 + tx*4] = o;
  }
}

__global__ void fuse_excited_kernel(){
  int idx = blockIdx.x*blockDim.x + threadIdx.x;
  if (idx >= MTOT*128) return;
  int m = idx >> 7, n = (idx & 127) << 2;
  int b = m >> 7, t = m & 127;
  float4 tot = make_float4(0.f, 0.f, 0.f, 0.f);
  #pragma unroll
  for (int k = 0; k < LL; k++){
    float4 mu = *(const float4*)&g_mul1[((size_t)k*MTOT + m)*HH + n];
    float4 hv = *(const float4*)&g_hh[(((size_t)(t+1)*LL + k)*BB + b)*HH + n];
    tot.x += mu.x*hv.x; tot.y += mu.y*hv.y; tot.z += mu.z*hv.z; tot.w += mu.w*hv.w;
  }
  float4 o = make_float4(fmaxf(tot.x,0.f), fmaxf(tot.y,0.f), fmaxf(tot.z,0.f), fmaxf(tot.w,0.f));
  *(float4*)&g_excited[(size_t)m*HH + n] = o;
}

__global__ void __launch_bounds__(256) e3_kernel(const float* __restrict__ Wo,
                                                 const float* __restrict__ bo,
                                                 float* __restrict__ out){
  __shared__ float Ash[32][68];
  __shared__ float Bsh[32][68];
  const int tid = threadIdx.x, tx = tid & 15, ty = tid >> 4;
  const int m0 = blockIdx.x*64;
  float acc[4][4] = {{0.f,0.f,0.f,0.f},{0.f,0.f,0.f,0.f},{0.f,0.f,0.f,0.f},{0.f,0.f,0.f,0.f}};
  for (int f0 = 0; f0 < HH; f0 += 32){
    load_tiles_T<32>(g_excited + (size_t)m0*HH, HH, 0, (const unsigned char*)g_z, f0,
                     Wo, HH, f0, tid, Ash, Bsh);
    __syncthreads();
    mm_inner(Ash, Bsh, 32, ty, tx, acc);
    __syncthreads();
  }
  #pragma unroll
  for (int r = 0; r < 4; r++){
    int n = tx*4;
    float4 o = make_float4(acc[r][0] + bo[n], acc[r][1] + bo[n+1],
                           acc[r][2] + bo[n+2], acc[r][3] + bo[n+3]);
    *(float4*)&out[(size_t)(m0 + ty*4 + r)*FF + n] = o;
  }
}

// ---------------- launch -----------------------------------------------------
extern "C" void kernel_launch(void* const* d_in, const int* in_sizes, int n_in,
                              void* d_out, int out_size) {
  const float* inp      = (const float*)d_in[0];
  const float* W        = (const float*)d_in[1];
  const float* Z        = (const float*)d_in[2];
  const float* U        = (const float*)d_in[3];
  const float* V        = (const float*)d_in[4];
  const float* Jm       = (const float*)d_in[5];
  const float* bvec     = (const float*)d_in[6];
  const float* boundary = (const float*)d_in[7];
  const float* Q        = (const float*)d_in[8];
  const float* Rm       = (const float*)d_in[9];
  const float* Wo       = (const float*)d_in[10];
  const float* bo       = (const float*)d_in[11];
  float* out            = (float*)d_out;

  prep_zero_kernel<<<512, 256>>>();
  prep_in_kernel<<<128, 256>>>(inp, boundary);
  prep_allz_kernel<<<2, 256>>>();

  trans_split_kernel<<<dim3(64, 16, 4), dim3(32, 8)>>>(Q,  g_QThi,  g_QTlo,  2048, 512);
  trans_split_kernel<<<dim3(16, 16, 4), dim3(32, 8)>>>(Rm, g_RmThi, g_RmTlo, 512,  512);

  recur_kernel<<<NREC, 256>>>(W, Z, U, V, Jm, bvec);

  conv_hcat_kernel<<<(MTOT*512)/256, 256>>>();
  e1_wmma_kernel<<<dim3(16, 64), 256>>>();
  verify_e1_kernel<<<16, 256>>>(Q);
  e1_fb_kernel<<<dim3(32, 128), 256>>>(Q);
  e2_wmma_kernel<<<dim3(4, 64, 4), 256>>>();
  verify_e2_kernel<<<16, 256>>>(Rm);
  e2_fb_kernel<<<dim3(8, 128, 4), 256>>>(Rm);
  fuse_excited_kernel<<<(MTOT*128)/256, 256>>>();
  e3_kernel<<<128, 256>>>(Wo, bo, out);
}

// round 17
// speedup vs baseline: 1.8804x; 1.0584x over previous
#include <cuda_runtime.h>
#include <cuda_bf16.h>
#include <mma.h>
#include <math.h>
#include <stdint.h>

using namespace nvcuda;

#define TT 128
#define LL 4
#define BB 64
#define HH 512
#define GG 16
#define FF 64
#define NREC 128
#define FIVEH (5*HH)
#define MTOT (BB*TT)   // 8192

// ---------------- scratch (device globals; no allocations) -------------------
__device__ __align__(128) float g_hh[(size_t)(TT+1)*LL*BB*HH];
__device__ __align__(128) float g_c[LL*BB*HH];
__device__ __align__(128) float g_xg[TT*LL*BB*GG];
__device__ unsigned char g_z[TT*LL*BB];
__device__ unsigned char g_allz[TT*LL];
__device__ float g_bt[LL*TT];
__device__ __align__(128) float g_part[TT*LL*NREC];
__device__ __align__(128) float g_pp [4*BB*4*HH];
__device__ __align__(128) float g_pp2[4*BB*4*HH];
__device__ unsigned int g_bar;
__device__ unsigned int g_flag1, g_flag2;
__device__ __align__(128) float g_excited[(size_t)MTOT*HH];

// bf16 split buffers for the excitation GEMMs (proven R10)
__device__ __align__(128) __nv_bfloat16 g_Ahi[(size_t)MTOT*2048];
__device__ __align__(128) __nv_bfloat16 g_Alo[(size_t)MTOT*2048];
__device__ __align__(128) __nv_bfloat16 g_QThi[(size_t)LL*HH*2048];
__device__ __align__(128) __nv_bfloat16 g_QTlo[(size_t)LL*HH*2048];
__device__ __align__(128) __nv_bfloat16 g_R1hi[(size_t)LL*MTOT*HH];
__device__ __align__(128) __nv_bfloat16 g_R1lo[(size_t)LL*MTOT*HH];
__device__ __align__(128) __nv_bfloat16 g_RmThi[(size_t)LL*HH*HH];
__device__ __align__(128) __nv_bfloat16 g_RmTlo[(size_t)LL*HH*HH];
__device__ __align__(128) float g_mul1[(size_t)LL*MTOT*HH];

__device__ __forceinline__ float sigf(float x){ return 1.f/(1.f+expf(-x)); }
__device__ __forceinline__ float clip01(float x){ return fminf(fmaxf(x,0.f),1.f); }
__device__ __forceinline__ void bsplit(float x, __nv_bfloat16& hi, __nv_bfloat16& lo){
  hi = __float2bfloat16(x);
  lo = __float2bfloat16(x - __bfloat162float(hi));
}

// ---------------- WMMA common (excitation only) ------------------------------
#define SPAD 40

using FragA = wmma::fragment<wmma::matrix_a,16,16,16,__nv_bfloat16,wmma::row_major>;
using FragB = wmma::fragment<wmma::matrix_b,16,16,16,__nv_bfloat16,wmma::col_major>;
using FragC = wmma::fragment<wmma::accumulator,16,16,16,float>;

__device__ __forceinline__ void wmma_core(
    __nv_bfloat16* sm,
    const __nv_bfloat16* __restrict__ Ah, const __nv_bfloat16* __restrict__ Al, int lda,
    const __nv_bfloat16* __restrict__ Bh, const __nv_bfloat16* __restrict__ Bl, int ldb,
    int ktot, FragC (&acc)[2][4])
{
  __nv_bfloat16* sAh = sm;
  __nv_bfloat16* sAl = sm +   128*SPAD;
  __nv_bfloat16* sBh = sm + 2*128*SPAD;
  __nv_bfloat16* sBl = sm + 3*128*SPAD;
  const int tid = threadIdx.x, wid = tid >> 5;
  const int wm = wid & 3, wn = wid >> 2;

  for (int kc = 0; kc < ktot; kc += 32){
    #pragma unroll
    for (int id = tid; id < 512; id += 256){
      int row = id >> 2, q = id & 3;
      *(uint4*)&sAh[row*SPAD + q*8] = *(const uint4*)&Ah[(size_t)row*lda + kc + q*8];
      *(uint4*)&sAl[row*SPAD + q*8] = *(const uint4*)&Al[(size_t)row*lda + kc + q*8];
      *(uint4*)&sBh[row*SPAD + q*8] = *(const uint4*)&Bh[(size_t)row*ldb + kc + q*8];
      *(uint4*)&sBl[row*SPAD + q*8] = *(const uint4*)&Bl[(size_t)row*ldb + kc + q*8];
    }
    __syncthreads();
    #pragma unroll
    for (int ks = 0; ks < 32; ks += 16){
      FragA fah[2], fal[2];
      #pragma unroll
      for (int mi = 0; mi < 2; mi++){
        wmma::load_matrix_sync(fah[mi], &sAh[(wm*32 + mi*16)*SPAD + ks], SPAD);
        wmma::load_matrix_sync(fal[mi], &sAl[(wm*32 + mi*16)*SPAD + ks], SPAD);
      }
      #pragma unroll
      for (int ni = 0; ni < 4; ni++){
        FragB fbh, fbl;
        wmma::load_matrix_sync(fbh, &sBh[(wn*64 + ni*16)*SPAD + ks], SPAD);
        wmma::load_matrix_sync(fbl, &sBl[(wn*64 + ni*16)*SPAD + ks], SPAD);
        #pragma unroll
        for (int mi = 0; mi < 2; mi++){
          wmma::mma_sync(acc[mi][ni], fah[mi], fbh, acc[mi][ni]);
          wmma::mma_sync(acc[mi][ni], fal[mi], fbh, acc[mi][ni]);
          wmma::mma_sync(acc[mi][ni], fah[mi], fbl, acc[mi][ni]);
        }
      }
    }
    __syncthreads();
  }
}

// ---------------- fp32 SIMT GEMM helpers (bit-exact R10) ---------------------
__device__ __forceinline__ void mm_inner(const float (*Ash)[68], const float (*Bsh)[68],
                                         int cw, int ty, int tx, float (&acc)[4][4]){
  #pragma unroll 8
  for (int j = 0; j < cw; j++){
    float4 av = *(const float4*)&Ash[j][ty*4];
    float4 bv = *(const float4*)&Bsh[j][tx*4];
    acc[0][0] += av.x*bv.x; acc[0][1] += av.x*bv.y; acc[0][2] += av.x*bv.z; acc[0][3] += av.x*bv.w;
    acc[1][0] += av.y*bv.x; acc[1][1] += av.y*bv.y; acc[1][2] += av.y*bv.z; acc[1][3] += av.y*bv.w;
    acc[2][0] += av.z*bv.x; acc[2][1] += av.z*bv.y; acc[2][2] += av.z*bv.z; acc[2][3] += av.z*bv.w;
    acc[3][0] += av.w*bv.x; acc[3][1] += av.w*bv.y; acc[3][2] += av.w*bv.z; acc[3][3] += av.w*bv.w;
  }
}

template<int CW>
__device__ __forceinline__ void load_tiles_T(
    const float* __restrict__ A, int lda, int mm, const unsigned char* zsh, int jba,
    const float* __restrict__ Wr, int wstr, int jbw,
    int tid, float (*Ash)[68], float (*Bsh)[68])
{
  const int QP = CW/4;
  const int NF4 = 64*QP;
  #pragma unroll
  for (int id = tid; id < NF4; id += 256){
    int row = id / QP, q = id - row*QP;
    float4 v = *(const float4*)&A[(size_t)row*lda + jba + q*4];
    if (mm == 1){ if (!zsh[row]) v = make_float4(0.f,0.f,0.f,0.f); }
    else if (mm == 2){ if (zsh[row]) v = make_float4(0.f,0.f,0.f,0.f); }
    int jj = q*4;
    Ash[jj][row]=v.x; Ash[jj+1][row]=v.y; Ash[jj+2][row]=v.z; Ash[jj+3][row]=v.w;
  }
  #pragma unroll
  for (int id = tid; id < NF4; id += 256){
    int n = id / QP, q = id - n*QP;
    float4 v = *(const float4*)&Wr[(size_t)n*wstr + jbw + q*4];
    int jj = q*4;
    Bsh[jj][n]=v.x; Bsh[jj+1][n]=v.y; Bsh[jj+2][n]=v.z; Bsh[jj+3][n]=v.w;
  }
}

// ---------------- preprocessing ----------------------------------------------
__global__ void prep_zero_kernel(){
  int idx = blockIdx.x*blockDim.x + threadIdx.x;
  if (idx < LL*BB*HH){ g_hh[idx] = 0.f; g_c[idx] = 0.f; }
  if (idx == 0){ g_bar = 0u; g_flag1 = 0u; g_flag2 = 0u; }
}

__global__ void prep_in_kernel(const float* __restrict__ inp,
                               const float* __restrict__ boundary){
  int idx = blockIdx.x*blockDim.x + threadIdx.x;
  if (idx < TT*LL*BB){
    int b  = idx % BB;
    int kk = (idx / BB) % LL;
    int t  = idx / (BB*LL);
    const float* src = inp + (b*TT + t)*FF + kk*GG;
    bool any = false;
    #pragma unroll
    for (int j = 0; j < GG; j++){
      float v = src[j];
      bool nn = (v != v);
      any = any || (!nn);
      g_xg[idx*GG + j] = nn ? 0.f : v;
    }
    g_z[idx] = any ? 1 : 0;
  }
  if (idx < LL*TT) g_bt[idx] = (boundary[idx] > 0.5f) ? 1.f : 0.f;
}

__global__ void prep_allz_kernel(){
  int st = blockIdx.x*blockDim.x + threadIdx.x;
  if (st < TT*LL){
    unsigned char a = 1;
    for (int b = 0; b < BB; b++) a = (unsigned char)(a & g_z[st*BB + b]);
    g_allz[st] = a;
  }
}

// ---------------- grid barrier -----------------------------------------------
__device__ __forceinline__ void gbar(unsigned int tgt){
  __syncthreads();
  if (threadIdx.x == 0){
    __threadfence();
    atomicAdd(&g_bar, 1u);
    while (*((volatile unsigned int*)&g_bar) < tgt) __nanosleep(32);
  }
  __syncthreads();
  __threadfence();
}

// ---------------- recurrence GEMM job (pipelined, value-exact R10) -----------
struct Chunk { const float* A; const float* Wr; int lda, wstr, jba, jbw, cw, mm; };

__device__ __forceinline__ void pref_chunk(const Chunk& c, int tid,
                                           float4 (&rA)[2], float4 (&rB)[2]){
  if (c.cw == 32){
    #pragma unroll
    for (int p = 0; p < 2; p++){
      int id = tid + p*256;
      int row = id >> 3, q = id & 7;
      rA[p] = *(const float4*)&c.A [(size_t)row*c.lda  + c.jba + q*4];
      rB[p] = *(const float4*)&c.Wr[(size_t)row*c.wstr + c.jbw + q*4];
    }
  } else {   // cw == 16
    int row = tid >> 2, q = tid & 3;
    rA[0] = *(const float4*)&c.A [(size_t)row*c.lda  + c.jba + q*4];
    rB[0] = *(const float4*)&c.Wr[(size_t)row*c.wstr + c.jbw + q*4];
    rA[1] = make_float4(0.f,0.f,0.f,0.f);
    rB[1] = make_float4(0.f,0.f,0.f,0.f);
  }
}

__device__ __forceinline__ void store_chunk(const Chunk& c, int tid, const unsigned char* zsh,
    const float4 (&rA)[2], const float4 (&rB)[2], float (*Ash)[68], float (*Bsh)[68]){
  if (c.cw == 32){
    #pragma unroll
    for (int p = 0; p < 2; p++){
      int id = tid + p*256;
      int row = id >> 3, q = id & 7;
      float4 v = rA[p];
      if (c.mm == 1){ if (!zsh[row]) v = make_float4(0.f,0.f,0.f,0.f); }
      else if (c.mm == 2){ if (zsh[row]) v = make_float4(0.f,0.f,0.f,0.f); }
      int jj = q*4;
      Ash[jj][row]=v.x; Ash[jj+1][row]=v.y; Ash[jj+2][row]=v.z; Ash[jj+3][row]=v.w;
      float4 w = rB[p];
      Bsh[jj][row]=w.x; Bsh[jj+1][row]=w.y; Bsh[jj+2][row]=w.z; Bsh[jj+3][row]=w.w;
    }
  } else {
    int row = tid >> 2, q = tid & 3;
    float4 v = rA[0];
    if (c.mm == 1){ if (!zsh[row]) v = make_float4(0.f,0.f,0.f,0.f); }
    else if (c.mm == 2){ if (zsh[row]) v = make_float4(0.f,0.f,0.f,0.f); }
    int jj = q*4;
    Ash[jj][row]=v.x; Ash[jj+1][row]=v.y; Ash[jj+2][row]=v.z; Ash[jj+3][row]=v.w;
    float4 w = rB[0];
    Bsh[jj][row]=w.x; Bsh[jj+1][row]=w.y; Bsh[jj+2][row]=w.z; Bsh[jj+3][row]=w.w;
  }
}

__device__ __forceinline__ void gemm_job(
    int t, int k, int mode, bool az, const unsigned char* zsh, int j, float* pp,
    const float* __restrict__ W, const float* __restrict__ Z,
    const float* __restrict__ U, const float* __restrict__ V,
    const float* __restrict__ Jm,
    int tid, int tx, int ty, float (*Ash)[68], float (*Bsh)[68])
{
  const int ng = (mode == 1) ? 4 : 3, nT = ng*8;
  const int split = j / nT, ntile = j - split*nT;
  const int n0 = ntile*64, loc = n0 >> 9, h0 = n0 & 511;
  const int g = (mode == 1) ? ((loc == 3) ? 4 : loc)
                            : ((loc == 0) ? 1 : ((loc == 1) ? 2 : 4));
  const size_t wr0 = (size_t)(g*HH + h0);
  const int jb = split*128;
  float acc[4][4] = {{0.f,0.f,0.f,0.f},{0.f,0.f,0.f,0.f},{0.f,0.f,0.f,0.f},{0.f,0.f,0.f,0.f}};

  // flat chunk list: same block order + K order as R10 (value-exact)
  Chunk ch[13]; int nc = 0;
  {
    const int km = (mode == 1) ? k : ((k+1 < LL) ? k+1 : LL-1);
    const float* A = g_hh + ((size_t)(t*LL + km)*BB)*HH;
    const float* Wr = ((mode == 1) ? W : Z) + (size_t)k*FIVEH*HH + wr0*HH;
    #pragma unroll
    for (int c4 = 0; c4 < 4; c4++)
      ch[nc++] = Chunk{A, Wr, HH, HH, jb + c4*32, jb + c4*32, 32, 0};
  }
  if (mode != 2 && k > 0){
    const float* hlow = g_hh + ((size_t)((t+1)*LL + (k-1))*BB)*HH;
    {
      const float* Wr = U + (size_t)k*FIVEH*(HH+GG) + wr0*(HH+GG);
      const int mm = az ? 0 : 1;
      #pragma unroll
      for (int c4 = 0; c4 < 4; c4++)
        ch[nc++] = Chunk{hlow, Wr, HH, HH+GG, jb + c4*32, jb + c4*32, 32, mm};
    }
    if (!az){
      const float* Wr = V + (size_t)k*FIVEH*HH + wr0*HH;
      #pragma unroll
      for (int c4 = 0; c4 < 4; c4++)
        ch[nc++] = Chunk{hlow, Wr, HH, HH, jb + c4*32, jb + c4*32, 32, 2};
    }
  }
  if (split == 0){
    const float* A = g_xg + (size_t)(t*LL + k)*BB*GG;
    if (mode != 2)
      ch[nc++] = Chunk{A, U + (size_t)k*FIVEH*(HH+GG) + wr0*(HH+GG), GG, HH+GG, 0, HH, 16, 0};
    else
      ch[nc++] = Chunk{A, Jm + (size_t)k*FIVEH*GG + wr0*GG, GG, GG, 0, 0, 16, 0};
  }

  // software pipeline: prefetch i+1 during mma of i
  float4 rA[2], rB[2];
  pref_chunk(ch[0], tid, rA, rB);
  for (int i = 0; i < nc; i++){
    __syncthreads();
    store_chunk(ch[i], tid, zsh, rA, rB, Ash, Bsh);
    __syncthreads();
    if (i+1 < nc) pref_chunk(ch[i+1], tid, rA, rB);
    mm_inner(Ash, Bsh, ch[i].cw, ty, tx, acc);
  }
  __syncthreads();

  #pragma unroll
  for (int r = 0; r < 4; r++){
    float4 o = make_float4(acc[r][0], acc[r][1], acc[r][2], acc[r][3]);
    *(float4*)&pp[((size_t)split*BB + ty*4 + r)*(4*HH) + n0 + tx*4] = o;
  }
}

// ---------------- per-stage epilogue (bit-exact R10 body) --------------------
__device__ __forceinline__ void epi_stage(
    int t, int k, int mode, const float* __restrict__ pp,
    const float* __restrict__ bvec, int tid, int cta, float* red)
{
  const float* bk = bvec + k*FIVEH;
  const int e = cta*256 + tid, eb = e >> 9, eh = e & 511;
  const size_t dsth = ((size_t)((t+1)*LL + k)*BB + eb)*HH + eh;
  const size_t srch = ((size_t)(t*LL + k)*BB + eb)*HH + eh;
  float sgv;
  if (mode == 4){
    float o  = sigf(bk[3*HH + eh]);
    float cp = g_c[(k*BB + eb)*HH + eh];
    g_hh[dsth] = o * tanhf(cp);
    sgv = clip01((bk[4*HH + eh] + 1.f)*0.5f);
  } else {
    const int ng = (mode == 1) ? 4 : 3;
    const size_t pb = (size_t)eb*(4*HH) + eh;
    const size_t sp = (size_t)BB*4*HH;
    float a0 = ((pp[pb]      + pp[sp + pb])      + pp[2*sp + pb])      + pp[3*sp + pb];
    float a1 = ((pp[pb+HH]   + pp[sp + pb+HH])   + pp[2*sp + pb+HH])   + pp[3*sp + pb+HH];
    float a2 = ((pp[pb+2*HH] + pp[sp + pb+2*HH]) + pp[2*sp + pb+2*HH]) + pp[3*sp + pb+2*HH];
    float a3 = 0.f;
    if (ng == 4)
      a3 = ((pp[pb+3*HH] + pp[sp + pb+3*HH]) + pp[2*sp + pb+3*HH]) + pp[3*sp + pb+3*HH];

    float cp = g_c[(k*BB + eb)*HH + eh];
    float cn, ps;
    if (mode == 1){
      float f  = sigf (a0 + bk[eh]);
      float gg = tanhf(a1 + bk[HH + eh]);
      float ii = sigf (a2 + bk[2*HH + eh]);
      ps = a3 + bk[4*HH + eh];
      cn = f*cp + ii*gg;
    } else {
      float gg = tanhf(a0 + bk[HH + eh]);
      float ii = sigf (a1 + bk[2*HH + eh]);
      ps = a2 + bk[4*HH + eh];
      cn = ii*gg;
    }
    g_c[(k*BB + eb)*HH + eh] = cn;
    g_hh[dsth] = g_hh[srch];
    sgv = clip01((ps + 1.f)*0.5f);
  }
  red[tid] = sgv; __syncthreads();
  #pragma unroll
  for (int s = 128; s > 0; s >>= 1){ if (tid < s) red[tid] += red[tid+s]; __syncthreads(); }
  if (tid == 0) g_part[(t*LL + k)*NREC + cta] = red[0];
  __syncthreads();
}

// ---------------- persistent recurrence: fp32, 2-stage wavefront -------------
__global__ void __launch_bounds__(256,1) recur_kernel(
    const float* __restrict__ W, const float* __restrict__ Z,
    const float* __restrict__ U, const float* __restrict__ V,
    const float* __restrict__ Jm, const float* __restrict__ bvec)
{
  __shared__ float Ash[32][68];
  __shared__ float Bsh[32][68];
  __shared__ float red[256];
  __shared__ float sfl[4];
  __shared__ unsigned char zshA[64], zshB[64];

  const int tid = threadIdx.x;
  const int cta = blockIdx.x;
  const int tx = tid & 15, ty = tid >> 4;
  unsigned int tgt = 0;

  for (int w = 0; w <= 2*(TT-1)+3; w++){       // 258 waves
    const int kA = (w & 1), kB = kA + 2;
    const int tA = (w - kA) >> 1, tB = (w - kB) >> 1;
    const bool hasA = (tA < TT);
    const bool hasB = (tB >= 0) && (tB < TT);
    const int stA = tA*LL + kA, stB = tB*LL + kB;

    // ---- flags (identical deterministic reductions on every CTA) ----
    if (hasA){
      float v = (tA > 0 && tid < NREC) ? g_part[(stA-LL)*NREC + tid] : 0.f;
      red[tid] = v; __syncthreads();
      #pragma unroll
      for (int s = 128; s > 0; s >>= 1){ if (tid < s) red[tid] += red[tid+s]; __syncthreads(); }
      if (tid == 0) sfl[0] = (tA == 0) ? g_bt[kA*TT] : ((red[0] > 16384.f) ? 1.f : 0.f);
      __syncthreads();
      v = (kA > 0 && tid < NREC) ? g_part[(stA-1)*NREC + tid] : 0.f;
      red[tid] = v; __syncthreads();
      #pragma unroll
      for (int s = 128; s > 0; s >>= 1){ if (tid < s) red[tid] += red[tid+s]; __syncthreads(); }
      if (tid == 0) sfl[1] = (kA == 0) ? g_bt[tA] : ((red[0] > 16384.f) ? 1.f : 0.f);
      __syncthreads();
    }
    if (hasB){
      float v = (tB > 0 && tid < NREC) ? g_part[(stB-LL)*NREC + tid] : 0.f;
      red[tid] = v; __syncthreads();
      #pragma unroll
      for (int s = 128; s > 0; s >>= 1){ if (tid < s) red[tid] += red[tid+s]; __syncthreads(); }
      if (tid == 0) sfl[2] = (tB == 0) ? g_bt[kB*TT] : ((red[0] > 16384.f) ? 1.f : 0.f);
      __syncthreads();
      v = g_part[(stB-1)*NREC + ((tid < NREC) ? tid : 0)];
      v = (tid < NREC) ? v : 0.f;
      red[tid] = v; __syncthreads();
      #pragma unroll
      for (int s = 128; s > 0; s >>= 1){ if (tid < s) red[tid] += red[tid+s]; __syncthreads(); }
      if (tid == 0) sfl[3] = (red[0] > 16384.f) ? 1.f : 0.f;
      __syncthreads();
    }
    if (tid < 64){
      if (hasA) zshA[tid] = g_z[stA*BB + tid];
      if (hasB) zshB[tid] = g_z[stB*BB + tid];
    }
    __syncthreads();

    int modeA = 4, modeB = 4;
    if (hasA){
      bool p = sfl[0] >= 0.5f, l = sfl[1] >= 0.5f;
      modeA = (!p && l) ? 1 : ((p && !l) ? 2 : ((p && l) ? 3 : 4));
    }
    if (hasB){
      bool p = sfl[2] >= 0.5f, l = sfl[3] >= 0.5f;
      modeB = (!p && l) ? 1 : ((p && !l) ? 2 : ((p && l) ? 3 : 4));
    }
    const bool azA = hasA && (g_allz[stA] != 0);
    const bool azB = hasB && (g_allz[stB] != 0);
    const int nJA = (hasA && modeA != 4) ? ((modeA == 1) ? 128 : 96) : 0;
    const int nJB = (hasB && modeB != 4) ? ((modeB == 1) ? 128 : 96) : 0;
    const int totJ = nJA + nJB;

    // ---- GEMM phase ----
    for (int gj = cta; gj < totJ; gj += NREC){
      if (gj < nJA)
        gemm_job(tA, kA, modeA, azA, zshA, gj, g_pp, W, Z, U, V, Jm, tid, tx, ty, Ash, Bsh);
      else
        gemm_job(tB, kB, modeB, azB, zshB, gj - nJA, g_pp2, W, Z, U, V, Jm, tid, tx, ty, Ash, Bsh);
    }
    if (totJ > 0){ tgt += NREC; gbar(tgt); }

    // ---- epilogues (A then B), then wave barrier ----
    if (hasA) epi_stage(tA, kA, modeA, g_pp,  bvec, tid, cta, red);
    if (hasB) epi_stage(tB, kB, modeB, g_pp2, bvec, tid, cta, red);
    tgt += NREC; gbar(tgt);
  }
}

// ---------------- bf16 split conversions (excitation) ------------------------
__global__ void conv_hcat_kernel(){
  int idx = blockIdx.x*blockDim.x + threadIdx.x;
  if (idx >= MTOT*512) return;
  int m = idx >> 9, f4 = (idx & 511);
  int f = f4*4;
  int b = m >> 7, t = m & 127;
  int kf = f >> 9, hf = f & 511;
  float4 v = *(const float4*)&g_hh[(((size_t)(t+1)*LL + kf)*BB + b)*HH + hf];
  union { __nv_bfloat16 e[4]; uint2 u; } wh, wl;
  bsplit(v.x, wh.e[0], wl.e[0]);
  bsplit(v.y, wh.e[1], wl.e[1]);
  bsplit(v.z, wh.e[2], wl.e[2]);
  bsplit(v.w, wh.e[3], wl.e[3]);
  *(uint2*)&g_Ahi[(size_t)m*2048 + f] = wh.u;
  *(uint2*)&g_Alo[(size_t)m*2048 + f] = wl.u;
}

__global__ void trans_split_kernel(const float* __restrict__ src,
                                   __nv_bfloat16* __restrict__ dhi,
                                   __nv_bfloat16* __restrict__ dlo,
                                   int R, int C){
  __shared__ float tl[32][33];
  const int z = blockIdx.z;
  const float* s = src + (size_t)z*R*C;
  __nv_bfloat16* oh = dhi + (size_t)z*R*C;
  __nv_bfloat16* ol = dlo + (size_t)z*R*C;
  int r0 = blockIdx.x*32, c0 = blockIdx.y*32;
  int tx = threadIdx.x, ty = threadIdx.y;
  #pragma unroll
  for (int i = 0; i < 4; i++)
    tl[ty + 8*i][tx] = s[(size_t)(r0 + ty + 8*i)*C + c0 + tx];
  __syncthreads();
  #pragma unroll
  for (int i = 0; i < 4; i++){
    float v = tl[tx][ty + 8*i];
    __nv_bfloat16 hi, lo; bsplit(v, hi, lo);
    size_t o = (size_t)(c0 + ty + 8*i)*R + r0 + tx;
    oh[o] = hi; ol[o] = lo;
  }
}

// ---------------- excitation: WMMA (proven R10) ------------------------------
__global__ void __launch_bounds__(256) e1_wmma_kernel(){
  __shared__ __align__(32) __nv_bfloat16 smbuf[4*128*SPAD];
  const int n0 = blockIdx.x*128, m0 = blockIdx.y*128;
  FragC acc[2][4];
  #pragma unroll
  for (int mi = 0; mi < 2; mi++)
    #pragma unroll
    for (int ni = 0; ni < 4; ni++) wmma::fill_fragment(acc[mi][ni], 0.f);

  wmma_core(smbuf,
            g_Ahi + (size_t)m0*2048, g_Alo + (size_t)m0*2048, 2048,
            g_QThi + (size_t)n0*2048, g_QTlo + (size_t)n0*2048, 2048,
            2048, acc);

  float* swp = (float*)smbuf;
  const int tid = threadIdx.x, lane = tid & 31, wid = tid >> 5;
  const int wm = wid & 3, wn = wid >> 2;
  const int kq = n0 >> 9, h0 = n0 & 511;
  float* wp = swp + wid*384;
  #pragma unroll
  for (int mi = 0; mi < 2; mi++){
    #pragma unroll
    for (int ni = 0; ni < 4; ni++){
      wmma::store_matrix_sync(wp, acc[mi][ni], 24, wmma::mem_row_major);
      __syncwarp();
      int r0 = m0 + wm*32 + mi*16;
      int c0 = h0 + wn*64 + ni*16;
      #pragma unroll
      for (int e = 0; e < 8; e++){
        int idx2 = e*32 + lane;
        int r = idx2 >> 4, c = idx2 & 15;
        float vv = sigf(wp[r*24 + c]);
        __nv_bfloat16 hi, lo; bsplit(vv, hi, lo);
        size_t o = ((size_t)kq*MTOT + r0 + r)*HH + c0 + c;
        g_R1hi[o] = hi; g_R1lo[o] = lo;
      }
      __syncwarp();
    }
  }
}

__global__ void __launch_bounds__(256) e2_wmma_kernel(){
  __shared__ __align__(32) __nv_bfloat16 smbuf[4*128*SPAD];
  const int n0 = blockIdx.x*128, m0 = blockIdx.y*128, kq = blockIdx.z;
  FragC acc[2][4];
  #pragma unroll
  for (int mi = 0; mi < 2; mi++)
    #pragma unroll
    for (int ni = 0; ni < 4; ni++) wmma::fill_fragment(acc[mi][ni], 0.f);

  wmma_core(smbuf,
            g_R1hi + ((size_t)kq*MTOT + m0)*HH, g_R1lo + ((size_t)kq*MTOT + m0)*HH, 512,
            g_RmThi + ((size_t)kq*HH + n0)*HH,  g_RmTlo + ((size_t)kq*HH + n0)*HH,  512,
            512, acc);

  const int wid = threadIdx.x >> 5;
  const int wm = wid & 3, wn = wid >> 2;
  #pragma unroll
  for (int mi = 0; mi < 2; mi++){
    #pragma unroll
    for (int ni = 0; ni < 4; ni++){
      int r0 = m0 + wm*32 + mi*16;
      int c0 = n0 + wn*64 + ni*16;
      wmma::store_matrix_sync(&g_mul1[((size_t)kq*MTOT + r0)*HH + c0],
                              acc[mi][ni], HH, wmma::mem_row_major);
    }
  }
}

// ---------------- verifiers (warp-collective) + SIMT fallbacks ---------------
__global__ void verify_e1_kernel(const float* __restrict__ Q){
  int s = (blockIdx.x*blockDim.x + threadIdx.x) >> 5;   // 256 warp-samples
  int lane = threadIdx.x & 31;
  int m = (s*131 + 7) & 8191;
  int c = (s*53 + 11) & 2047;
  int kq = c >> 9, h = c & 511;
  int b = m >> 7, t = m & 127;
  float acc = 0.f;
  for (int f = lane; f < 2048; f += 32){
    int kf = f >> 9, hf = f & 511;
    acc += g_hh[(((size_t)(t+1)*LL + kf)*BB + b)*HH + hf] * Q[((size_t)kq*2048 + f)*512 + h];
  }
  #pragma unroll
  for (int o = 16; o > 0; o >>= 1) acc += __shfl_xor_sync(0xffffffffu, acc, o);
  if (lane == 0){
    float want = sigf(acc);
    size_t o = ((size_t)kq*MTOT + m)*HH + h;
    float got = __bfloat162float(g_R1hi[o]) + __bfloat162float(g_R1lo[o]);
    float d = fabsf(got - want);
    if (!(d <= 2e-3f)) atomicExch(&g_flag1, 1u);
  }
}

__global__ void __launch_bounds__(256) e1_fb_kernel(const float* __restrict__ Q){
  if (g_flag1 == 0u) return;
  __shared__ float Ash[32][68];
  __shared__ float Bsh[32][68];
  const int tid = threadIdx.x, tx = tid & 15, ty = tid >> 4;
  const int n0 = blockIdx.x*64, m0 = blockIdx.y*64;
  const int kq = n0 >> 9, nh0 = n0 & 511;
  const int bB = m0 >> 7, t0 = m0 & 127;
  float acc[4][4] = {{0.f,0.f,0.f,0.f},{0.f,0.f,0.f,0.f},{0.f,0.f,0.f,0.f},{0.f,0.f,0.f,0.f}};
  for (int f0 = 0; f0 < LL*HH; f0 += 32){
    const int kf = f0 >> 9, hf = f0 & 511;
    const float* abase = g_hh + ((size_t)(t0+1)*LL + kf)*BB*HH + (size_t)bB*HH + hf;
    #pragma unroll
    for (int id = tid; id < 512; id += 256){
      int mi = id >> 3, q = id & 7;
      float4 v = *(const float4*)(abase + (size_t)mi*(LL*BB*HH) + q*4);
      int jj = q*4;
      Ash[jj][mi]=v.x; Ash[jj+1][mi]=v.y; Ash[jj+2][mi]=v.z; Ash[jj+3][mi]=v.w;
    }
    #pragma unroll
    for (int id = tid; id < 512; id += 256){
      int j = id >> 4, qn = id & 15;
      float4 v = *(const float4*)&Q[((size_t)kq*(LL*HH) + f0 + j)*HH + nh0 + qn*4];
      *(float4*)&Bsh[j][qn*4] = v;
    }
    __syncthreads();
    mm_inner(Ash, Bsh, 32, ty, tx, acc);
    __syncthreads();
  }
  #pragma unroll
  for (int r = 0; r < 4; r++){
    #pragma unroll
    for (int c = 0; c < 4; c++){
      float vv = sigf(acc[r][c]);
      __nv_bfloat16 hi, lo; bsplit(vv, hi, lo);
      size_t o = ((size_t)kq*MTOT + m0 + ty*4 + r)*HH + nh0 + tx*4 + c;
      g_R1hi[o] = hi; g_R1lo[o] = lo;
    }
  }
}

__global__ void verify_e2_kernel(const float* __restrict__ Rm){
  int s = (blockIdx.x*blockDim.x + threadIdx.x) >> 5;   // 256 warp-samples
  int lane = threadIdx.x & 31;
  int m = (s*131 + 7) & 8191;
  int g = (s*53 + 11) & 511;
  int kq = s & 3;
  float acc = 0.f;
  for (int h = lane; h < 512; h += 32){
    size_t o = ((size_t)kq*MTOT + m)*HH + h;
    float r1 = __bfloat162float(g_R1hi[o]) + __bfloat162float(g_R1lo[o]);
    acc += r1 * Rm[((size_t)kq*512 + h)*512 + g];
  }
  #pragma unroll
  for (int o = 16; o > 0; o >>= 1) acc += __shfl_xor_sync(0xffffffffu, acc, o);
  if (lane == 0){
    float got = g_mul1[((size_t)kq*MTOT + m)*HH + g];
    float d = fabsf(got - acc);
    if (!(d <= 5e-3f)) atomicExch(&g_flag2, 1u);
  }
}

__global__ void __launch_bounds__(256) e2_fb_kernel(const float* __restrict__ Rm){
  if (g_flag2 == 0u) return;
  __shared__ float Ash[32][68];
  __shared__ float Bsh[32][68];
  const int tid = threadIdx.x, tx = tid & 15, ty = tid >> 4;
  const int n0 = blockIdx.x*64, m0 = blockIdx.y*64, kq = blockIdx.z;
  float acc[4][4] = {{0.f,0.f,0.f,0.f},{0.f,0.f,0.f,0.f},{0.f,0.f,0.f,0.f},{0.f,0.f,0.f,0.f}};
  for (int f0 = 0; f0 < HH; f0 += 32){
    #pragma unroll
    for (int id = tid; id < 2048; id += 256){
      int mi = id >> 5, j = id & 31;
      size_t o = ((size_t)kq*MTOT + m0 + mi)*HH + f0 + j;
      Ash[j][mi] = __bfloat162float(g_R1hi[o]) + __bfloat162float(g_R1lo[o]);
    }
    #pragma unroll
    for (int id = tid; id < 512; id += 256){
      int j = id >> 4, qn = id & 15;
      float4 v = *(const float4*)&Rm[((size_t)kq*HH + f0 + j)*HH + n0 + qn*4];
      *(float4*)&Bsh[j][qn*4] = v;
    }
    __syncthreads();
    mm_inner(Ash, Bsh, 32, ty, tx, acc);
    __syncthreads();
  }
  #pragma unroll
  for (int r = 0; r < 4; r++){
    float4 o = make_float4(acc[r][0], acc[r][1], acc[r][2], acc[r][3]);
    *(float4*)&g_mul1[((size_t)kq*MTOT + m0 + ty*4 + r)*HH + n0 + tx*4] = o;
  }
}

__global__ void fuse_excited_kernel(){
  int idx = blockIdx.x*blockDim.x + threadIdx.x;
  if (idx >= MTOT*128) return;
  int m = idx >> 7, n = (idx & 127) << 2;
  int b = m >> 7, t = m & 127;
  float4 tot = make_float4(0.f, 0.f, 0.f, 0.f);
  #pragma unroll
  for (int k = 0; k < LL; k++){
    float4 mu = *(const float4*)&g_mul1[((size_t)k*MTOT + m)*HH + n];
    float4 hv = *(const float4*)&g_hh[(((size_t)(t+1)*LL + k)*BB + b)*HH + n];
    tot.x += mu.x*hv.x; tot.y += mu.y*hv.y; tot.z += mu.z*hv.z; tot.w += mu.w*hv.w;
  }
  float4 o = make_float4(fmaxf(tot.x,0.f), fmaxf(tot.y,0.f), fmaxf(tot.z,0.f), fmaxf(tot.w,0.f));
  *(float4*)&g_excited[(size_t)m*HH + n] = o;
}

__global__ void __launch_bounds__(256) e3_kernel(const float* __restrict__ Wo,
                                                 const float* __restrict__ bo,
                                                 float* __restrict__ out){
  __shared__ float Ash[32][68];
  __shared__ float Bsh[32][68];
  const int tid = threadIdx.x, tx = tid & 15, ty = tid >> 4;
  const int m0 = blockIdx.x*64;
  float acc[4][4] = {{0.f,0.f,0.f,0.f},{0.f,0.f,0.f,0.f},{0.f,0.f,0.f,0.f},{0.f,0.f,0.f,0.f}};
  for (int f0 = 0; f0 < HH; f0 += 32){
    load_tiles_T<32>(g_excited + (size_t)m0*HH, HH, 0, (const unsigned char*)g_z, f0,
                     Wo, HH, f0, tid, Ash, Bsh);
    __syncthreads();
    mm_inner(Ash, Bsh, 32, ty, tx, acc);
    __syncthreads();
  }
  #pragma unroll
  for (int r = 0; r < 4; r++){
    int n = tx*4;
    float4 o = make_float4(acc[r][0] + bo[n], acc[r][1] + bo[n+1],
                           acc[r][2] + bo[n+2], acc[r][3] + bo[n+3]);
    *(float4*)&out[(size_t)(m0 + ty*4 + r)*FF + n] = o;
  }
}

// ---------------- launch -----------------------------------------------------
extern "C" void kernel_launch(void* const* d_in, const int* in_sizes, int n_in,
                              void* d_out, int out_size) {
  const float* inp      = (const float*)d_in[0];
  const float* W        = (const float*)d_in[1];
  const float* Z        = (const float*)d_in[2];
  const float* U        = (const float*)d_in[3];
  const float* V        = (const float*)d_in[4];
  const float* Jm       = (const float*)d_in[5];
  const float* bvec     = (const float*)d_in[6];
  const float* boundary = (const float*)d_in[7];
  const float* Q        = (const float*)d_in[8];
  const float* Rm       = (const float*)d_in[9];
  const float* Wo       = (const float*)d_in[10];
  const float* bo       = (const float*)d_in[11];
  float* out            = (float*)d_out;

  prep_zero_kernel<<<512, 256>>>();
  prep_in_kernel<<<128, 256>>>(inp, boundary);
  prep_allz_kernel<<<2, 256>>>();

  trans_split_kernel<<<dim3(64, 16, 4), dim3(32, 8)>>>(Q,  g_QThi,  g_QTlo,  2048, 512);
  trans_split_kernel<<<dim3(16, 16, 4), dim3(32, 8)>>>(Rm, g_RmThi, g_RmTlo, 512,  512);

  recur_kernel<<<NREC, 256>>>(W, Z, U, V, Jm, bvec);

  conv_hcat_kernel<<<(MTOT*512)/256, 256>>>();
  e1_wmma_kernel<<<dim3(16, 64), 256>>>();
  verify_e1_kernel<<<32, 256>>>(Q);
  e1_fb_kernel<<<dim3(32, 128), 256>>>(Q);
  e2_wmma_kernel<<<dim3(4, 64, 4), 256>>>();
  verify_e2_kernel<<<32, 256>>>(Rm);
  e2_fb_kernel<<<dim3(8, 128, 4), 256>>>(Rm);
  fuse_excited_kernel<<<(MTOT*128)/256, 256>>>();
  e3_kernel<<<128, 256>>>(Wo, bo, out);
}